// round 2
// baseline (speedup 1.0000x reference)
#include <cuda_runtime.h>
#include <math.h>

// ---------------------------------------------------------------------------
// Problem constants
// ---------------------------------------------------------------------------
constexpr int BATCH = 4;
constexpr int SEQ   = 2048;
constexpr int DIM   = 768;
constexpr int GDIM  = 256;   // per-group embed
constexpr int HDIM  = 64;    // head dim (4 heads per group)
constexpr int MROWS = BATCH * SEQ;   // 8192
constexpr float DT_F  = 0.05f;
constexpr float HJ_HF = 0.05f;

// ---------------------------------------------------------------------------
// Device scratch (no cudaMalloc allowed)
// ---------------------------------------------------------------------------
__device__ float g_h[MROWS * DIM];          // input projection
__device__ float g_qkv[3][MROWS * DIM];     // per-group qkv (B,T,768)
__device__ float g_attn[MROWS * DIM];       // attention outputs, groups at col g*256
__device__ float g_u[MROWS * DIM];          // post out-proj / PDE state, groups at col g*256

// ---------------------------------------------------------------------------
// Generic tiled GEMM with bias: C[M,N] = A[M,K] @ B[K,N] + bias[N]
// BM=128, BN=64, BK=16, 256 threads, 8x4 register tile per thread.
// All M,N,K used here divide the tile sizes exactly.
// ---------------------------------------------------------------------------
__global__ void gemm_bias_kernel(const float* __restrict__ A, int lda,
                                 const float* __restrict__ Bm, int ldb,
                                 const float* __restrict__ bias,
                                 float* __restrict__ C, int ldc,
                                 int K)
{
    __shared__ float As[16][128];   // transposed A tile: As[k][m]
    __shared__ float Bs[16][64];

    const int tid = threadIdx.x;
    const int tx = tid & 15;        // col group (4 cols)
    const int ty = tid >> 4;        // row group (8 rows)
    const int bm = blockIdx.y * 128;
    const int bn = blockIdx.x * 64;

    float acc[8][4];
    #pragma unroll
    for (int i = 0; i < 8; ++i)
        #pragma unroll
        for (int j = 0; j < 4; ++j) acc[i][j] = 0.f;

    const int a_row = tid >> 2;          // 0..63
    const int a_col = (tid & 3) * 4;     // 0,4,8,12
    const int b_row = tid >> 4;          // 0..15
    const int b_col = (tid & 15) * 4;    // 0..60

    for (int k0 = 0; k0 < K; k0 += 16) {
        #pragma unroll
        for (int r = 0; r < 2; ++r) {
            int row = a_row + r * 64;
            float4 v = *reinterpret_cast<const float4*>(
                A + (size_t)(bm + row) * lda + k0 + a_col);
            As[a_col + 0][row] = v.x;
            As[a_col + 1][row] = v.y;
            As[a_col + 2][row] = v.z;
            As[a_col + 3][row] = v.w;
        }
        {
            float4 w = *reinterpret_cast<const float4*>(
                Bm + (size_t)(k0 + b_row) * ldb + bn + b_col);
            *reinterpret_cast<float4*>(&Bs[b_row][b_col]) = w;
        }
        __syncthreads();

        #pragma unroll
        for (int kk = 0; kk < 16; ++kk) {
            float4 a0 = *reinterpret_cast<const float4*>(&As[kk][ty * 8]);
            float4 a1 = *reinterpret_cast<const float4*>(&As[kk][ty * 8 + 4]);
            float4 b0 = *reinterpret_cast<const float4*>(&Bs[kk][tx * 4]);
            const float av[8] = {a0.x, a0.y, a0.z, a0.w, a1.x, a1.y, a1.z, a1.w};
            const float bv[4] = {b0.x, b0.y, b0.z, b0.w};
            #pragma unroll
            for (int i = 0; i < 8; ++i)
                #pragma unroll
                for (int j = 0; j < 4; ++j)
                    acc[i][j] += av[i] * bv[j];
        }
        __syncthreads();
    }

    #pragma unroll
    for (int i = 0; i < 8; ++i) {
        int row = bm + ty * 8 + i;
        int col = bn + tx * 4;
        float4 o;
        o.x = acc[i][0] + bias[col + 0];
        o.y = acc[i][1] + bias[col + 1];
        o.z = acc[i][2] + bias[col + 2];
        o.w = acc[i][3] + bias[col + 3];
        *reinterpret_cast<float4*>(C + (size_t)row * ldc + col) = o;
    }
}

// ---------------------------------------------------------------------------
// Streaming causal attention (flash-style), 64x64 tiles, head_dim = 64.
// grid = (SEQ/64, BATCH*4 heads, 3 groups); block = 256 threads (16x16).
// qkv layout per group: (B,T,768) with q|k|v at col offsets 0/256/512, head h
// at +h*64. Output written into g_attn at column offset g*256 + h*64.
// ---------------------------------------------------------------------------
constexpr int ATT_SMEM_BYTES = (3 * 64 * 68 + 64 * 65) * 4;   // 68,864 B

__global__ void attn_kernel(const float* __restrict__ qkv_all,
                            float* __restrict__ attn_out)
{
    extern __shared__ float sm[];
    float (*Qst)[68] = (float(*)[68])(sm);                 // [d][row]
    float (*Kst)[68] = (float(*)[68])(sm + 64 * 68);       // [d][key]
    float (*Vs )[68] = (float(*)[68])(sm + 2 * 64 * 68);   // [key][d]
    float (*Ps )[65] = (float(*)[65])(sm + 3 * 64 * 68);   // [row][key]

    const int tid = threadIdx.x;
    const int tx = tid & 15;
    const int ty = tid >> 4;
    const int qt = blockIdx.x;
    const int b  = blockIdx.y >> 2;
    const int h  = blockIdx.y & 3;
    const int g  = blockIdx.z;
    const int q0 = qt * 64;

    const float* base = qkv_all + (size_t)g * MROWS * DIM + (size_t)b * SEQ * DIM;
    float* outp = attn_out + (size_t)g * GDIM;
    const int qoff = h * HDIM;
    const int koff = GDIM + h * HDIM;
    const int voff = 2 * GDIM + h * HDIM;

    // Load Q tile, transposed into Qst[d][row]
    {
        const int r  = tid >> 2;
        const int c4 = (tid & 3) * 4;
        #pragma unroll
        for (int it = 0; it < 4; ++it) {
            int c = c4 + it * 16;
            float4 v = *reinterpret_cast<const float4*>(
                base + (size_t)(q0 + r) * DIM + qoff + c);
            Qst[c + 0][r] = v.x; Qst[c + 1][r] = v.y;
            Qst[c + 2][r] = v.z; Qst[c + 3][r] = v.w;
        }
    }

    float mrow[4], lrow[4], oacc[4][4];
    #pragma unroll
    for (int i = 0; i < 4; ++i) {
        mrow[i] = -1e30f; lrow[i] = 0.f;
        #pragma unroll
        for (int j = 0; j < 4; ++j) oacc[i][j] = 0.f;
    }

    for (int jt = 0; jt <= qt; ++jt) {
        __syncthreads();   // prior iteration done reading Kst/Vs/Ps; Q visible
        const int j0 = jt * 64;
        {
            const int r  = tid >> 2;
            const int c4 = (tid & 3) * 4;
            #pragma unroll
            for (int it = 0; it < 4; ++it) {
                int c = c4 + it * 16;
                float4 kv = *reinterpret_cast<const float4*>(
                    base + (size_t)(j0 + r) * DIM + koff + c);
                Kst[c + 0][r] = kv.x; Kst[c + 1][r] = kv.y;
                Kst[c + 2][r] = kv.z; Kst[c + 3][r] = kv.w;
                float4 vv = *reinterpret_cast<const float4*>(
                    base + (size_t)(j0 + r) * DIM + voff + c);
                *reinterpret_cast<float4*>(&Vs[r][c]) = vv;
            }
        }
        __syncthreads();

        // S = Q K^T
        float s[4][4];
        #pragma unroll
        for (int i = 0; i < 4; ++i)
            #pragma unroll
            for (int j = 0; j < 4; ++j) s[i][j] = 0.f;

        #pragma unroll 8
        for (int kk = 0; kk < 64; ++kk) {
            float4 qv = *reinterpret_cast<const float4*>(&Qst[kk][ty * 4]);
            float4 kv = *reinterpret_cast<const float4*>(&Kst[kk][tx * 4]);
            const float qa[4] = {qv.x, qv.y, qv.z, qv.w};
            const float kb[4] = {kv.x, kv.y, kv.z, kv.w};
            #pragma unroll
            for (int i = 0; i < 4; ++i)
                #pragma unroll
                for (int j = 0; j < 4; ++j)
                    s[i][j] += qa[i] * kb[j];
        }

        // scale + causal mask (diagonal tile only)
        #pragma unroll
        for (int i = 0; i < 4; ++i)
            #pragma unroll
            for (int j = 0; j < 4; ++j) {
                s[i][j] *= 0.125f;
                if (jt == qt && (tx * 4 + j) > (ty * 4 + i)) s[i][j] = -1e30f;
            }

        // online softmax, rows owned by 16-lane segments (same ty)
        #pragma unroll
        for (int i = 0; i < 4; ++i) {
            float rm = s[i][0];
            #pragma unroll
            for (int j = 1; j < 4; ++j) rm = fmaxf(rm, s[i][j]);
            rm = fmaxf(rm, __shfl_xor_sync(0xffffffffu, rm, 8, 16));
            rm = fmaxf(rm, __shfl_xor_sync(0xffffffffu, rm, 4, 16));
            rm = fmaxf(rm, __shfl_xor_sync(0xffffffffu, rm, 2, 16));
            rm = fmaxf(rm, __shfl_xor_sync(0xffffffffu, rm, 1, 16));
            float mnew  = fmaxf(mrow[i], rm);
            float alpha = __expf(mrow[i] - mnew);
            mrow[i] = mnew;
            float rs = 0.f;
            #pragma unroll
            for (int j = 0; j < 4; ++j) {
                s[i][j] = __expf(s[i][j] - mnew);
                rs += s[i][j];
            }
            rs += __shfl_xor_sync(0xffffffffu, rs, 8, 16);
            rs += __shfl_xor_sync(0xffffffffu, rs, 4, 16);
            rs += __shfl_xor_sync(0xffffffffu, rs, 2, 16);
            rs += __shfl_xor_sync(0xffffffffu, rs, 1, 16);
            lrow[i] = lrow[i] * alpha + rs;
            #pragma unroll
            for (int j = 0; j < 4; ++j) oacc[i][j] *= alpha;
        }

        // stage P for the PV GEMM
        #pragma unroll
        for (int i = 0; i < 4; ++i)
            #pragma unroll
            for (int j = 0; j < 4; ++j)
                Ps[ty * 4 + i][tx * 4 + j] = s[i][j];
        __syncthreads();

        // O += P V
        #pragma unroll 8
        for (int kk = 0; kk < 64; ++kk) {
            float4 vv = *reinterpret_cast<const float4*>(&Vs[kk][tx * 4]);
            float pv[4];
            #pragma unroll
            for (int i = 0; i < 4; ++i) pv[i] = Ps[ty * 4 + i][kk];
            #pragma unroll
            for (int i = 0; i < 4; ++i) {
                oacc[i][0] += pv[i] * vv.x;
                oacc[i][1] += pv[i] * vv.y;
                oacc[i][2] += pv[i] * vv.z;
                oacc[i][3] += pv[i] * vv.w;
            }
        }
    }

    #pragma unroll
    for (int i = 0; i < 4; ++i) {
        float inv = 1.0f / lrow[i];
        float4 ov = make_float4(oacc[i][0] * inv, oacc[i][1] * inv,
                                oacc[i][2] * inv, oacc[i][3] * inv);
        size_t row = (size_t)b * SEQ + q0 + ty * 4 + i;
        *reinterpret_cast<float4*>(outp + row * DIM + h * HDIM + tx * 4) = ov;
    }
}

// ---------------------------------------------------------------------------
// PDE kernels: one block per (batch, channel) column, column in shared memory.
// u points at the group's column base (stride DIM between timesteps).
// ---------------------------------------------------------------------------
__global__ void pde_sg_kernel(float* __restrict__ u)
{
    const int b = blockIdx.x >> 8;
    const int c = blockIdx.x & 255;
    float* col = u + (size_t)b * SEQ * DIM + c;
    __shared__ float su[SEQ], sw[SEQ];
    const int tid = threadIdx.x;

    for (int t = tid; t < SEQ; t += 256) { su[t] = col[(size_t)t * DIM]; sw[t] = 0.f; }
    __syncthreads();

    for (int step = 0; step < 3; ++step) {
        float dw[8];
        #pragma unroll
        for (int i = 0; i < 8; ++i) {
            int t = tid + i * 256;
            float um = (t > 0)       ? su[t - 1] : 0.f;
            float up = (t < SEQ - 1) ? su[t + 1] : 0.f;
            dw[i] = DT_F * ((um - 2.f * su[t] + up) - sinf(su[t]));
        }
        __syncthreads();
        #pragma unroll
        for (int i = 0; i < 8; ++i) {
            int t = tid + i * 256;
            sw[t] += dw[i];
            su[t] += DT_F * sw[t];
        }
        __syncthreads();
    }
    for (int t = tid; t < SEQ; t += 256) col[(size_t)t * DIM] = su[t];
}

__global__ void pde_kdv_kernel(float* __restrict__ u)
{
    const int b = blockIdx.x >> 8;
    const int c = blockIdx.x & 255;
    float* col = u + (size_t)b * SEQ * DIM + c;
    __shared__ float su[SEQ];
    const int tid = threadIdx.x;

    for (int t = tid; t < SEQ; t += 256) su[t] = col[(size_t)t * DIM];
    __syncthreads();

    for (int step = 0; step < 3; ++step) {
        float du[8];
        #pragma unroll
        for (int i = 0; i < 8; ++i) {
            int t = tid + i * 256;
            float um2 = (t > 1)       ? su[t - 2] : 0.f;
            float um1 = (t > 0)       ? su[t - 1] : 0.f;
            float up1 = (t < SEQ - 1) ? su[t + 1] : 0.f;
            float up2 = (t < SEQ - 2) ? su[t + 2] : 0.f;
            float d1 = 0.5f * (up1 - um1);
            float d3 = 0.5f * (up2 - 2.f * up1 + 2.f * um1 - um2);
            du[i] = DT_F * (-6.f * su[t] * d1 - d3);
        }
        __syncthreads();
        #pragma unroll
        for (int i = 0; i < 8; ++i) {
            int t = tid + i * 256;
            su[t] += du[i];
        }
        __syncthreads();
    }
    for (int t = tid; t < SEQ; t += 256) col[(size_t)t * DIM] = su[t];
}

__global__ void pde_hj_kernel(float* __restrict__ u)
{
    const int b = blockIdx.x >> 8;
    const int c = blockIdx.x & 255;
    float* col = u + (size_t)b * SEQ * DIM + c;
    __shared__ float su[SEQ], sw[SEQ], sf[SEQ];
    const int tid = threadIdx.x;

    for (int t = tid; t < SEQ; t += 256) { su[t] = col[(size_t)t * DIM]; sw[t] = 0.f; }
    __syncthreads();

    for (int step = 0; step < 3; ++step) {
        #pragma unroll
        for (int i = 0; i < 8; ++i) {
            int t = tid + i * 256;
            float v = su[t];
            sf[t] = v - v * v + v * v * v;
        }
        __syncthreads();
        float dw[8];
        #pragma unroll
        for (int i = 0; i < 8; ++i) {
            int t = tid + i * 256;
            float fm  = (t > 0)       ? sf[t - 1] : 0.f;
            float fp  = (t < SEQ - 1) ? sf[t + 1] : 0.f;
            float d2f = fm - 2.f * sf[t] + fp;
            float um2 = (t > 1)       ? su[t - 2] : 0.f;
            float um1 = (t > 0)       ? su[t - 1] : 0.f;
            float up1 = (t < SEQ - 1) ? su[t + 1] : 0.f;
            float up2 = (t < SEQ - 2) ? su[t + 2] : 0.f;
            float d4  = um2 - 4.f * um1 + 6.f * su[t] - 4.f * up1 + up2;
            dw[i] = DT_F * (d2f - HJ_HF * d4);
        }
        __syncthreads();
        #pragma unroll
        for (int i = 0; i < 8; ++i) {
            int t = tid + i * 256;
            sw[t] += dw[i];
            su[t] += DT_F * sw[t];
        }
        __syncthreads();
    }
    for (int t = tid; t < SEQ; t += 256) col[(size_t)t * DIM] = su[t];
}

// ---------------------------------------------------------------------------
// Launch
// ---------------------------------------------------------------------------
extern "C" void kernel_launch(void* const* d_in, const int* in_sizes, int n_in,
                              void* d_out, int out_size)
{
    const float* x      = (const float*)d_in[0];
    const float* in_w   = (const float*)d_in[1];
    const float* in_b   = (const float*)d_in[2];
    const float* qkv_w[3] = {(const float*)d_in[3],  (const float*)d_in[7],  (const float*)d_in[11]};
    const float* qkv_b[3] = {(const float*)d_in[4],  (const float*)d_in[8],  (const float*)d_in[12]};
    const float* ow[3]    = {(const float*)d_in[5],  (const float*)d_in[9],  (const float*)d_in[13]};
    const float* ob[3]    = {(const float*)d_in[6],  (const float*)d_in[10], (const float*)d_in[14]};
    const float* out_w  = (const float*)d_in[15];
    const float* out_b  = (const float*)d_in[16];
    float* out = (float*)d_out;

    float *h, *qkv, *attn, *u;
    cudaGetSymbolAddress((void**)&h,    g_h);
    cudaGetSymbolAddress((void**)&qkv,  g_qkv);
    cudaGetSymbolAddress((void**)&attn, g_attn);
    cudaGetSymbolAddress((void**)&u,    g_u);

    cudaFuncSetAttribute(attn_kernel,
                         cudaFuncAttributeMaxDynamicSharedMemorySize,
                         ATT_SMEM_BYTES);

    // 1) h = x @ in_w + in_b
    gemm_bias_kernel<<<dim3(DIM / 64, MROWS / 128), 256>>>(
        x, DIM, in_w, DIM, in_b, h, DIM, DIM);

    // 2) per-group qkv = h[:, g*256:(g+1)*256] @ qkv_w_g + qkv_b_g
    for (int g = 0; g < 3; ++g) {
        gemm_bias_kernel<<<dim3(768 / 64, MROWS / 128), 256>>>(
            h + g * GDIM, DIM, qkv_w[g], 768, qkv_b[g],
            qkv + (size_t)g * MROWS * DIM, 768, GDIM);
    }

    // 3) causal attention, all 3 groups in one launch
    attn_kernel<<<dim3(SEQ / 64, BATCH * 4, 3), 256, ATT_SMEM_BYTES>>>(qkv, attn);

    // 4) per-group out projection into u (concat layout)
    for (int g = 0; g < 3; ++g) {
        gemm_bias_kernel<<<dim3(GDIM / 64, MROWS / 128), 256>>>(
            attn + g * GDIM, DIM, ow[g], GDIM, ob[g],
            u + g * GDIM, DIM, GDIM);
    }

    // 5) PDE evolutions (in place on u)
    pde_sg_kernel <<<BATCH * GDIM, 256>>>(u + 0 * GDIM);
    pde_kdv_kernel<<<BATCH * GDIM, 256>>>(u + 1 * GDIM);
    pde_hj_kernel <<<BATCH * GDIM, 256>>>(u + 2 * GDIM);

    // 6) out = u @ out_w + out_b
    gemm_bias_kernel<<<dim3(DIM / 64, MROWS / 128), 256>>>(
        u, DIM, out_w, DIM, out_b, out, DIM, DIM);
}

// round 4
// speedup vs baseline: 1.3358x; 1.3358x over previous
#include <cuda_runtime.h>
#include <cuda_bf16.h>
#include <math.h>
#include <stdint.h>

// ---------------------------------------------------------------------------
// Problem constants
// ---------------------------------------------------------------------------
constexpr int BATCH = 4;
constexpr int SEQ   = 2048;
constexpr int DIM   = 768;
constexpr int GDIM  = 256;
constexpr int HDIM  = 64;
constexpr int MROWS = BATCH * SEQ;   // 8192
constexpr float DT_F  = 0.05f;
constexpr float HJ_HF = 0.05f;

// ---------------------------------------------------------------------------
// Device scratch (no cudaMalloc allowed)
// ---------------------------------------------------------------------------
__device__ float g_h[MROWS * DIM];
__device__ float g_qkv[3][MROWS * DIM];
__device__ float g_attn[MROWS * DIM];
__device__ float g_u[MROWS * DIM];

// Transposed + bf16-split weights: layout [N][K] per weight, hi and lo planes.
constexpr int WT_IN   = 0;
constexpr int WT_QKV0 = WT_IN   + 768 * 768;
constexpr int WT_OW0  = WT_QKV0 + 3 * 768 * 256;
constexpr int WT_OUT  = WT_OW0  + 3 * 256 * 256;
constexpr int WT_TOTAL = WT_OUT + 768 * 768;
__device__ __nv_bfloat16 g_whi[WT_TOTAL];
__device__ __nv_bfloat16 g_wlo[WT_TOTAL];

// ---------------------------------------------------------------------------
// Helpers
// ---------------------------------------------------------------------------
__device__ __forceinline__ uint32_t smem_u32(const void* p) {
    uint32_t a;
    asm("{ .reg .u64 t; cvta.to.shared.u64 t, %1; cvt.u32.u64 %0, t; }"
        : "=r"(a) : "l"(p));
    return a;
}
__device__ __forceinline__ void split_bf(float v, __nv_bfloat16& h, __nv_bfloat16& l) {
    h = __float2bfloat16_rn(v);
    l = __float2bfloat16_rn(v - __bfloat162float(h));
}
__device__ __forceinline__ uint32_t pack_bf2(__nv_bfloat16 a, __nv_bfloat16 b) {
    uint16_t ua = *reinterpret_cast<uint16_t*>(&a);
    uint16_t ub = *reinterpret_cast<uint16_t*>(&b);
    return (uint32_t)ua | ((uint32_t)ub << 16);
}
__device__ __forceinline__ void ldsm_x4(uint32_t* r, uint32_t a) {
    asm volatile("ldmatrix.sync.aligned.m8n8.x4.shared.b16 {%0,%1,%2,%3}, [%4];"
        : "=r"(r[0]), "=r"(r[1]), "=r"(r[2]), "=r"(r[3]) : "r"(a));
}
__device__ __forceinline__ void ldsm_x2(uint32_t* r, uint32_t a) {
    asm volatile("ldmatrix.sync.aligned.m8n8.x2.shared.b16 {%0,%1}, [%2];"
        : "=r"(r[0]), "=r"(r[1]) : "r"(a));
}
__device__ __forceinline__ void mma_bf16(float* c, const uint32_t* a, const uint32_t* b) {
    asm volatile("mma.sync.aligned.m16n8k16.row.col.f32.bf16.bf16.f32 "
        "{%0,%1,%2,%3}, {%4,%5,%6,%7}, {%8,%9}, {%0,%1,%2,%3};"
        : "+f"(c[0]), "+f"(c[1]), "+f"(c[2]), "+f"(c[3])
        : "r"(a[0]), "r"(a[1]), "r"(a[2]), "r"(a[3]), "r"(b[0]), "r"(b[1]));
}
__device__ __forceinline__ void cp_async16(uint32_t d, const void* s) {
    asm volatile("cp.async.ca.shared.global [%0], [%1], 16;" :: "r"(d), "l"(s) : "memory");
}
__device__ __forceinline__ void cp_commit() {
    asm volatile("cp.async.commit_group;" ::: "memory");
}
__device__ __forceinline__ void cp_wait0() {
    asm volatile("cp.async.wait_group 0;" ::: "memory");
}

// ---------------------------------------------------------------------------
// Weight prep: W[K][N] fp32 -> Whi/Wlo bf16, transposed [N][K].
// grid (N/32, K/32), block (32,8)
// ---------------------------------------------------------------------------
__global__ void wsplit_kernel(const float* __restrict__ W, int K, int N,
                              __nv_bfloat16* __restrict__ Whi,
                              __nv_bfloat16* __restrict__ Wlo)
{
    __shared__ float tile[32][33];
    const int kb = blockIdx.y * 32;
    const int nb = blockIdx.x * 32;
    const int tx = threadIdx.x;
    for (int i = threadIdx.y; i < 32; i += 8)
        tile[i][tx] = W[(size_t)(kb + i) * N + nb + tx];
    __syncthreads();
    for (int i = threadIdx.y; i < 32; i += 8) {
        float v = tile[tx][i];               // W[kb+tx][nb+i]
        __nv_bfloat16 h, l;
        split_bf(v, h, l);
        size_t o = (size_t)(nb + i) * K + kb + tx;
        Whi[o] = h;
        Wlo[o] = l;
    }
}

// ---------------------------------------------------------------------------
// bf16x3 HMMA GEMM: C[M,N] = A[M,K] @ W[K,N] + bias.
// A fp32 (split on the fly), W pre-split bf16 [N][K].
// Block 128x128x32, 256 threads (8 warps, 2x4), warp tile 64x32.
// Double-buffered SMEM, padded rows (32+8 bf16 = 80B) for conflict-free ldmatrix.
// ---------------------------------------------------------------------------
constexpr int GPLANE = 128 * 40 * 2;          // 10240 B per plane
constexpr int GSTAGE = 4 * GPLANE;            // Ahi|Alo|Bhi|Blo = 40960 B
constexpr int GEMM_SMEM = 2 * GSTAGE;         // 81920 B

__global__ __launch_bounds__(256)
void gemm_bf16x3_kernel(const float* __restrict__ A, int lda, int K,
                        const __nv_bfloat16* __restrict__ Whi,
                        const __nv_bfloat16* __restrict__ Wlo,
                        const float* __restrict__ bias,
                        float* __restrict__ C, int ldc)
{
    extern __shared__ char smc[];
    const uint32_t sbase = smem_u32(smc);

    const int tid  = threadIdx.x;
    const int lane = tid & 31;
    const int wid  = tid >> 5;
    const int wm   = wid & 1;          // 0..1 -> m offset wm*64
    const int wn   = wid >> 1;         // 0..3 -> n offset wn*32
    const int m0 = blockIdx.y * 128;
    const int n0 = blockIdx.x * 128;
    const int KT = K / 32;

    float acc[4][4][4];
    #pragma unroll
    for (int i = 0; i < 4; ++i)
        #pragma unroll
        for (int j = 0; j < 4; ++j)
            #pragma unroll
            for (int k = 0; k < 4; ++k) acc[i][j][k] = 0.f;

    // A load mapping: 128 rows x 32 floats; thread -> row=tid/2, col half
    const int arow = tid >> 1;
    const int acol = (tid & 1) * 16;
    const float* aptr = A + (size_t)(m0 + arow) * lda + acol;

    float4 areg[4];

    // ---- stage loaders ----
    auto fetch_A = [&](int kt) {
        #pragma unroll
        for (int i = 0; i < 4; ++i)
            areg[i] = *reinterpret_cast<const float4*>(aptr + kt * 32 + i * 4);
    };
    auto store_A = [&](int stage) {
        char* bh = smc + stage * GSTAGE + 0      + arow * 80 + acol * 2;
        char* bl = smc + stage * GSTAGE + GPLANE + arow * 80 + acol * 2;
        #pragma unroll
        for (int i = 0; i < 4; ++i) {
            float4 v = areg[i];
            __nv_bfloat16 h0, h1, h2, h3, l0, l1, l2, l3;
            split_bf(v.x, h0, l0); split_bf(v.y, h1, l1);
            split_bf(v.z, h2, l2); split_bf(v.w, h3, l3);
            uint2 ph = make_uint2(pack_bf2(h0, h1), pack_bf2(h2, h3));
            uint2 pl = make_uint2(pack_bf2(l0, l1), pack_bf2(l2, l3));
            *reinterpret_cast<uint2*>(bh + i * 8) = ph;
            *reinterpret_cast<uint2*>(bl + i * 8) = pl;
        }
    };
    auto load_B = [&](int kt, int stage) {
        #pragma unroll
        for (int j = 0; j < 2; ++j) {
            int cid = tid + 256 * j;
            int row = cid >> 2;
            int k8  = (cid & 3) * 8;
            size_t go = (size_t)(n0 + row) * K + kt * 32 + k8;
            uint32_t dh = sbase + stage * GSTAGE + 2 * GPLANE + row * 80 + k8 * 2;
            uint32_t dl = sbase + stage * GSTAGE + 3 * GPLANE + row * 80 + k8 * 2;
            cp_async16(dh, Whi + go);
            cp_async16(dl, Wlo + go);
        }
    };

    // ldmatrix lane addressing constants
    const int la_row = lane & 15;
    const int la_k   = (lane >> 4) * 8;
    const int lb_row = lane & 7;
    const int lb_k   = ((lane >> 3) & 1) * 8;

    auto compute = [&](int stage) {
        const uint32_t st = sbase + stage * GSTAGE;
        #pragma unroll
        for (int ks = 0; ks < 32; ks += 16) {
            uint32_t bh[4][2], bl[4][2];
            #pragma unroll
            for (int nt = 0; nt < 4; ++nt) {
                uint32_t rb = st + 2 * GPLANE
                            + (wn * 32 + nt * 8 + lb_row) * 80 + (ks + lb_k) * 2;
                ldsm_x2(bh[nt], rb);
                ldsm_x2(bl[nt], rb + GPLANE);
            }
            #pragma unroll
            for (int mt = 0; mt < 4; ++mt) {
                uint32_t ra = st
                            + (wm * 64 + mt * 16 + la_row) * 80 + (ks + la_k) * 2;
                uint32_t ah[4], al[4];
                ldsm_x4(ah, ra);
                ldsm_x4(al, ra + GPLANE);
                #pragma unroll
                for (int nt = 0; nt < 4; ++nt) {
                    mma_bf16(acc[mt][nt], ah, bh[nt]);
                    mma_bf16(acc[mt][nt], ah, bl[nt]);
                    mma_bf16(acc[mt][nt], al, bh[nt]);
                }
            }
        }
    };

    // ---- pipeline ----
    fetch_A(0);
    load_B(0, 0);
    cp_commit();
    store_A(0);
    cp_wait0();
    __syncthreads();

    for (int kt = 0; kt < KT; ++kt) {
        const int p = kt & 1;
        const bool more = (kt + 1 < KT);
        if (more) {
            fetch_A(kt + 1);
            load_B(kt + 1, p ^ 1);
            cp_commit();
        }
        compute(p);
        if (more) {
            store_A(p ^ 1);
            cp_wait0();
        }
        __syncthreads();
    }

    // ---- epilogue ----
    #pragma unroll
    for (int mt = 0; mt < 4; ++mt) {
        int r0 = m0 + wm * 64 + mt * 16 + (lane >> 2);
        #pragma unroll
        for (int nt = 0; nt < 4; ++nt) {
            int col = n0 + wn * 32 + nt * 8 + (lane & 3) * 2;
            float2 bv = *reinterpret_cast<const float2*>(bias + col);
            float2 o0 = make_float2(acc[mt][nt][0] + bv.x, acc[mt][nt][1] + bv.y);
            float2 o1 = make_float2(acc[mt][nt][2] + bv.x, acc[mt][nt][3] + bv.y);
            *reinterpret_cast<float2*>(C + (size_t)r0 * ldc + col) = o0;
            *reinterpret_cast<float2*>(C + (size_t)(r0 + 8) * ldc + col) = o1;
        }
    }
}

// ---------------------------------------------------------------------------
// Streaming causal attention (flash-style, SIMT), 64x64 tiles, head_dim = 64.
// PsT stored transposed [k][row] so the PV loop is pure LDS.128.
// ---------------------------------------------------------------------------
constexpr int ATT_SMEM_BYTES = 4 * 64 * 68 * 4;   // Qst|Kst|Vs|PsT

__global__ void attn_kernel(const float* __restrict__ qkv_all,
                            float* __restrict__ attn_out)
{
    extern __shared__ float sm[];
    float (*Qst)[68] = (float(*)[68])(sm);                 // [d][row]
    float (*Kst)[68] = (float(*)[68])(sm + 64 * 68);       // [d][key]
    float (*Vs )[68] = (float(*)[68])(sm + 2 * 64 * 68);   // [key][d]
    float (*PsT)[68] = (float(*)[68])(sm + 3 * 64 * 68);   // [key][row]

    const int tid = threadIdx.x;
    const int tx = tid & 15;
    const int ty = tid >> 4;
    const int qt = blockIdx.x;
    const int b  = blockIdx.y >> 2;
    const int h  = blockIdx.y & 3;
    const int g  = blockIdx.z;
    const int q0 = qt * 64;

    const float* base = qkv_all + (size_t)g * MROWS * DIM + (size_t)b * SEQ * DIM;
    float* outp = attn_out + (size_t)g * GDIM;
    const int qoff = h * HDIM;
    const int koff = GDIM + h * HDIM;
    const int voff = 2 * GDIM + h * HDIM;

    {
        const int r  = tid >> 2;
        const int c4 = (tid & 3) * 4;
        #pragma unroll
        for (int it = 0; it < 4; ++it) {
            int c = c4 + it * 16;
            float4 v = *reinterpret_cast<const float4*>(
                base + (size_t)(q0 + r) * DIM + qoff + c);
            Qst[c + 0][r] = v.x; Qst[c + 1][r] = v.y;
            Qst[c + 2][r] = v.z; Qst[c + 3][r] = v.w;
        }
    }

    float mrow[4], lrow[4], oacc[4][4];
    #pragma unroll
    for (int i = 0; i < 4; ++i) {
        mrow[i] = -1e30f; lrow[i] = 0.f;
        #pragma unroll
        for (int j = 0; j < 4; ++j) oacc[i][j] = 0.f;
    }

    for (int jt = 0; jt <= qt; ++jt) {
        __syncthreads();
        const int j0 = jt * 64;
        {
            const int r  = tid >> 2;
            const int c4 = (tid & 3) * 4;
            #pragma unroll
            for (int it = 0; it < 4; ++it) {
                int c = c4 + it * 16;
                float4 kv = *reinterpret_cast<const float4*>(
                    base + (size_t)(j0 + r) * DIM + koff + c);
                Kst[c + 0][r] = kv.x; Kst[c + 1][r] = kv.y;
                Kst[c + 2][r] = kv.z; Kst[c + 3][r] = kv.w;
                float4 vv = *reinterpret_cast<const float4*>(
                    base + (size_t)(j0 + r) * DIM + voff + c);
                *reinterpret_cast<float4*>(&Vs[r][c]) = vv;
            }
        }
        __syncthreads();

        float s[4][4];
        #pragma unroll
        for (int i = 0; i < 4; ++i)
            #pragma unroll
            for (int j = 0; j < 4; ++j) s[i][j] = 0.f;

        #pragma unroll 8
        for (int kk = 0; kk < 64; ++kk) {
            float4 qv = *reinterpret_cast<const float4*>(&Qst[kk][ty * 4]);
            float4 kv = *reinterpret_cast<const float4*>(&Kst[kk][tx * 4]);
            const float qa[4] = {qv.x, qv.y, qv.z, qv.w};
            const float kb[4] = {kv.x, kv.y, kv.z, kv.w};
            #pragma unroll
            for (int i = 0; i < 4; ++i)
                #pragma unroll
                for (int j = 0; j < 4; ++j)
                    s[i][j] += qa[i] * kb[j];
        }

        #pragma unroll
        for (int i = 0; i < 4; ++i)
            #pragma unroll
            for (int j = 0; j < 4; ++j) {
                s[i][j] *= 0.125f;
                if (jt == qt && (tx * 4 + j) > (ty * 4 + i)) s[i][j] = -1e30f;
            }

        #pragma unroll
        for (int i = 0; i < 4; ++i) {
            float rm = s[i][0];
            #pragma unroll
            for (int j = 1; j < 4; ++j) rm = fmaxf(rm, s[i][j]);
            rm = fmaxf(rm, __shfl_xor_sync(0xffffffffu, rm, 8, 16));
            rm = fmaxf(rm, __shfl_xor_sync(0xffffffffu, rm, 4, 16));
            rm = fmaxf(rm, __shfl_xor_sync(0xffffffffu, rm, 2, 16));
            rm = fmaxf(rm, __shfl_xor_sync(0xffffffffu, rm, 1, 16));
            float mnew  = fmaxf(mrow[i], rm);
            float alpha = __expf(mrow[i] - mnew);
            mrow[i] = mnew;
            float rs = 0.f;
            #pragma unroll
            for (int j = 0; j < 4; ++j) {
                s[i][j] = __expf(s[i][j] - mnew);
                rs += s[i][j];
            }
            rs += __shfl_xor_sync(0xffffffffu, rs, 8, 16);
            rs += __shfl_xor_sync(0xffffffffu, rs, 4, 16);
            rs += __shfl_xor_sync(0xffffffffu, rs, 2, 16);
            rs += __shfl_xor_sync(0xffffffffu, rs, 1, 16);
            lrow[i] = lrow[i] * alpha + rs;
            #pragma unroll
            for (int j = 0; j < 4; ++j) oacc[i][j] *= alpha;
        }

        // stage P transposed: PsT[key][row]
        #pragma unroll
        for (int i = 0; i < 4; ++i)
            #pragma unroll
            for (int j = 0; j < 4; ++j)
                PsT[tx * 4 + j][ty * 4 + i] = s[i][j];
        __syncthreads();

        // O += P V  (both operands via LDS.128)
        #pragma unroll 8
        for (int kk = 0; kk < 64; ++kk) {
            float4 pv = *reinterpret_cast<const float4*>(&PsT[kk][ty * 4]);
            float4 vv = *reinterpret_cast<const float4*>(&Vs[kk][tx * 4]);
            const float pa[4] = {pv.x, pv.y, pv.z, pv.w};
            #pragma unroll
            for (int i = 0; i < 4; ++i) {
                oacc[i][0] += pa[i] * vv.x;
                oacc[i][1] += pa[i] * vv.y;
                oacc[i][2] += pa[i] * vv.z;
                oacc[i][3] += pa[i] * vv.w;
            }
        }
    }

    #pragma unroll
    for (int i = 0; i < 4; ++i) {
        float inv = 1.0f / lrow[i];
        float4 ov = make_float4(oacc[i][0] * inv, oacc[i][1] * inv,
                                oacc[i][2] * inv, oacc[i][3] * inv);
        size_t row = (size_t)b * SEQ + q0 + ty * 4 + i;
        *reinterpret_cast<float4*>(outp + row * DIM + h * HDIM + tx * 4) = ov;
    }
}

// ---------------------------------------------------------------------------
// PDE kernels (unchanged, known good)
// ---------------------------------------------------------------------------
__global__ void pde_sg_kernel(float* __restrict__ u)
{
    const int b = blockIdx.x >> 8;
    const int c = blockIdx.x & 255;
    float* col = u + (size_t)b * SEQ * DIM + c;
    __shared__ float su[SEQ], sw[SEQ];
    const int tid = threadIdx.x;
    for (int t = tid; t < SEQ; t += 256) { su[t] = col[(size_t)t * DIM]; sw[t] = 0.f; }
    __syncthreads();
    for (int step = 0; step < 3; ++step) {
        float dw[8];
        #pragma unroll
        for (int i = 0; i < 8; ++i) {
            int t = tid + i * 256;
            float um = (t > 0)       ? su[t - 1] : 0.f;
            float up = (t < SEQ - 1) ? su[t + 1] : 0.f;
            dw[i] = DT_F * ((um - 2.f * su[t] + up) - sinf(su[t]));
        }
        __syncthreads();
        #pragma unroll
        for (int i = 0; i < 8; ++i) {
            int t = tid + i * 256;
            sw[t] += dw[i];
            su[t] += DT_F * sw[t];
        }
        __syncthreads();
    }
    for (int t = tid; t < SEQ; t += 256) col[(size_t)t * DIM] = su[t];
}

__global__ void pde_kdv_kernel(float* __restrict__ u)
{
    const int b = blockIdx.x >> 8;
    const int c = blockIdx.x & 255;
    float* col = u + (size_t)b * SEQ * DIM + c;
    __shared__ float su[SEQ];
    const int tid = threadIdx.x;
    for (int t = tid; t < SEQ; t += 256) su[t] = col[(size_t)t * DIM];
    __syncthreads();
    for (int step = 0; step < 3; ++step) {
        float du[8];
        #pragma unroll
        for (int i = 0; i < 8; ++i) {
            int t = tid + i * 256;
            float um2 = (t > 1)       ? su[t - 2] : 0.f;
            float um1 = (t > 0)       ? su[t - 1] : 0.f;
            float up1 = (t < SEQ - 1) ? su[t + 1] : 0.f;
            float up2 = (t < SEQ - 2) ? su[t + 2] : 0.f;
            float d1 = 0.5f * (up1 - um1);
            float d3 = 0.5f * (up2 - 2.f * up1 + 2.f * um1 - um2);
            du[i] = DT_F * (-6.f * su[t] * d1 - d3);
        }
        __syncthreads();
        #pragma unroll
        for (int i = 0; i < 8; ++i) {
            int t = tid + i * 256;
            su[t] += du[i];
        }
        __syncthreads();
    }
    for (int t = tid; t < SEQ; t += 256) col[(size_t)t * DIM] = su[t];
}

__global__ void pde_hj_kernel(float* __restrict__ u)
{
    const int b = blockIdx.x >> 8;
    const int c = blockIdx.x & 255;
    float* col = u + (size_t)b * SEQ * DIM + c;
    __shared__ float su[SEQ], sw[SEQ], sf[SEQ];
    const int tid = threadIdx.x;
    for (int t = tid; t < SEQ; t += 256) { su[t] = col[(size_t)t * DIM]; sw[t] = 0.f; }
    __syncthreads();
    for (int step = 0; step < 3; ++step) {
        #pragma unroll
        for (int i = 0; i < 8; ++i) {
            int t = tid + i * 256;
            float v = su[t];
            sf[t] = v - v * v + v * v * v;
        }
        __syncthreads();
        float dw[8];
        #pragma unroll
        for (int i = 0; i < 8; ++i) {
            int t = tid + i * 256;
            float fm  = (t > 0)       ? sf[t - 1] : 0.f;
            float fp  = (t < SEQ - 1) ? sf[t + 1] : 0.f;
            float d2f = fm - 2.f * sf[t] + fp;
            float um2 = (t > 1)       ? su[t - 2] : 0.f;
            float um1 = (t > 0)       ? su[t - 1] : 0.f;
            float up1 = (t < SEQ - 1) ? su[t + 1] : 0.f;
            float up2 = (t < SEQ - 2) ? su[t + 2] : 0.f;
            float d4  = um2 - 4.f * um1 + 6.f * su[t] - 4.f * up1 + up2;
            dw[i] = DT_F * (d2f - HJ_HF * d4);
        }
        __syncthreads();
        #pragma unroll
        for (int i = 0; i < 8; ++i) {
            int t = tid + i * 256;
            sw[t] += dw[i];
            su[t] += DT_F * sw[t];
        }
        __syncthreads();
    }
    for (int t = tid; t < SEQ; t += 256) col[(size_t)t * DIM] = su[t];
}

// ---------------------------------------------------------------------------
// Launch
// ---------------------------------------------------------------------------
extern "C" void kernel_launch(void* const* d_in, const int* in_sizes, int n_in,
                              void* d_out, int out_size)
{
    const float* x      = (const float*)d_in[0];
    const float* in_w   = (const float*)d_in[1];
    const float* in_b   = (const float*)d_in[2];
    const float* qkv_w[3] = {(const float*)d_in[3],  (const float*)d_in[7],  (const float*)d_in[11]};
    const float* qkv_b[3] = {(const float*)d_in[4],  (const float*)d_in[8],  (const float*)d_in[12]};
    const float* ow[3]    = {(const float*)d_in[5],  (const float*)d_in[9],  (const float*)d_in[13]};
    const float* ob[3]    = {(const float*)d_in[6],  (const float*)d_in[10], (const float*)d_in[14]};
    const float* out_w  = (const float*)d_in[15];
    const float* out_b  = (const float*)d_in[16];
    float* out = (float*)d_out;

    float *h, *qkv, *attn, *u;
    __nv_bfloat16 *whi, *wlo;
    cudaGetSymbolAddress((void**)&h,    g_h);
    cudaGetSymbolAddress((void**)&qkv,  g_qkv);
    cudaGetSymbolAddress((void**)&attn, g_attn);
    cudaGetSymbolAddress((void**)&u,    g_u);
    cudaGetSymbolAddress((void**)&whi,  g_whi);
    cudaGetSymbolAddress((void**)&wlo,  g_wlo);

    cudaFuncSetAttribute(attn_kernel,
                         cudaFuncAttributeMaxDynamicSharedMemorySize, ATT_SMEM_BYTES);
    cudaFuncSetAttribute(gemm_bf16x3_kernel,
                         cudaFuncAttributeMaxDynamicSharedMemorySize, GEMM_SMEM);

    dim3 wsb(32, 8);
    wsplit_kernel<<<dim3(768 / 32, 768 / 32), wsb>>>(in_w, 768, 768,
                                                     whi + WT_IN, wlo + WT_IN);
    for (int g = 0; g < 3; ++g)
        wsplit_kernel<<<dim3(768 / 32, 256 / 32), wsb>>>(
            qkv_w[g], 256, 768,
            whi + WT_QKV0 + g * 768 * 256, wlo + WT_QKV0 + g * 768 * 256);
    for (int g = 0; g < 3; ++g)
        wsplit_kernel<<<dim3(256 / 32, 256 / 32), wsb>>>(
            ow[g], 256, 256,
            whi + WT_OW0 + g * 256 * 256, wlo + WT_OW0 + g * 256 * 256);
    wsplit_kernel<<<dim3(768 / 32, 768 / 32), wsb>>>(out_w, 768, 768,
                                                     whi + WT_OUT, wlo + WT_OUT);

    // 1) h = x @ in_w + in_b
    gemm_bf16x3_kernel<<<dim3(768 / 128, MROWS / 128), 256, GEMM_SMEM>>>(
        x, DIM, 768, whi + WT_IN, wlo + WT_IN, in_b, h, DIM);

    // 2) per-group qkv
    for (int g = 0; g < 3; ++g)
        gemm_bf16x3_kernel<<<dim3(768 / 128, MROWS / 128), 256, GEMM_SMEM>>>(
            h + g * GDIM, DIM, 256,
            whi + WT_QKV0 + g * 768 * 256, wlo + WT_QKV0 + g * 768 * 256,
            qkv_b[g], qkv + (size_t)g * MROWS * DIM, DIM);

    // 3) causal attention
    attn_kernel<<<dim3(SEQ / 64, BATCH * 4, 3), 256, ATT_SMEM_BYTES>>>(qkv, attn);

    // 4) per-group out projection
    for (int g = 0; g < 3; ++g)
        gemm_bf16x3_kernel<<<dim3(256 / 128, MROWS / 128), 256, GEMM_SMEM>>>(
            attn + g * GDIM, DIM, 256,
            whi + WT_OW0 + g * 256 * 256, wlo + WT_OW0 + g * 256 * 256,
            ob[g], u + g * GDIM, DIM);

    // 5) PDE evolutions
    pde_sg_kernel <<<BATCH * GDIM, 256>>>(u + 0 * GDIM);
    pde_kdv_kernel<<<BATCH * GDIM, 256>>>(u + 1 * GDIM);
    pde_hj_kernel <<<BATCH * GDIM, 256>>>(u + 2 * GDIM);

    // 6) out = u @ out_w + out_b
    gemm_bf16x3_kernel<<<dim3(768 / 128, MROWS / 128), 256, GEMM_SMEM>>>(
        u, DIM, 768, whi + WT_OUT, wlo + WT_OUT, out_b, out, DIM);
}

// round 5
// speedup vs baseline: 2.0792x; 1.5565x over previous
#include <cuda_runtime.h>
#include <cuda_bf16.h>
#include <math.h>
#include <stdint.h>

// ---------------------------------------------------------------------------
// Problem constants
// ---------------------------------------------------------------------------
constexpr int BATCH = 4;
constexpr int SEQ   = 2048;
constexpr int DIM   = 768;
constexpr int GDIM  = 256;
constexpr int HDIM  = 64;
constexpr int MROWS = BATCH * SEQ;   // 8192
constexpr float DT_F  = 0.05f;
constexpr float HJ_HF = 0.05f;

// ---------------------------------------------------------------------------
// Device scratch (no cudaMalloc allowed)
// ---------------------------------------------------------------------------
__device__ float g_h[MROWS * DIM];
__device__ float g_qkv[3][MROWS * DIM];
__device__ float g_attn[MROWS * DIM];
__device__ float g_u[MROWS * DIM];

constexpr int WT_IN   = 0;
constexpr int WT_QKV0 = WT_IN   + 768 * 768;
constexpr int WT_OW0  = WT_QKV0 + 3 * 768 * 256;
constexpr int WT_OUT  = WT_OW0  + 3 * 256 * 256;
constexpr int WT_TOTAL = WT_OUT + 768 * 768;
__device__ __nv_bfloat16 g_whi[WT_TOTAL];
__device__ __nv_bfloat16 g_wlo[WT_TOTAL];

// ---------------------------------------------------------------------------
// Helpers
// ---------------------------------------------------------------------------
__device__ __forceinline__ uint32_t smem_u32(const void* p) {
    uint32_t a;
    asm("{ .reg .u64 t; cvta.to.shared.u64 t, %1; cvt.u32.u64 %0, t; }"
        : "=r"(a) : "l"(p));
    return a;
}
__device__ __forceinline__ void split_bf(float v, __nv_bfloat16& h, __nv_bfloat16& l) {
    h = __float2bfloat16_rn(v);
    l = __float2bfloat16_rn(v - __bfloat162float(h));
}
__device__ __forceinline__ uint32_t pack_bf2(__nv_bfloat16 a, __nv_bfloat16 b) {
    uint16_t ua = *reinterpret_cast<uint16_t*>(&a);
    uint16_t ub = *reinterpret_cast<uint16_t*>(&b);
    return (uint32_t)ua | ((uint32_t)ub << 16);
}
// pack hi bf16 pair, return lo pair through ref
__device__ __forceinline__ uint32_t packsplit(float a, float b, uint32_t& lo) {
    __nv_bfloat16 ha = __float2bfloat16_rn(a), hb = __float2bfloat16_rn(b);
    __nv_bfloat16 la = __float2bfloat16_rn(a - __bfloat162float(ha));
    __nv_bfloat16 lb = __float2bfloat16_rn(b - __bfloat162float(hb));
    lo = pack_bf2(la, lb);
    return pack_bf2(ha, hb);
}
__device__ __forceinline__ void ldsm_x4(uint32_t* r, uint32_t a) {
    asm volatile("ldmatrix.sync.aligned.m8n8.x4.shared.b16 {%0,%1,%2,%3}, [%4];"
        : "=r"(r[0]), "=r"(r[1]), "=r"(r[2]), "=r"(r[3]) : "r"(a));
}
__device__ __forceinline__ void ldsm_x2(uint32_t* r, uint32_t a) {
    asm volatile("ldmatrix.sync.aligned.m8n8.x2.shared.b16 {%0,%1}, [%2];"
        : "=r"(r[0]), "=r"(r[1]) : "r"(a));
}
__device__ __forceinline__ void mma_bf16(float* c, const uint32_t* a, const uint32_t* b) {
    asm volatile("mma.sync.aligned.m16n8k16.row.col.f32.bf16.bf16.f32 "
        "{%0,%1,%2,%3}, {%4,%5,%6,%7}, {%8,%9}, {%0,%1,%2,%3};"
        : "+f"(c[0]), "+f"(c[1]), "+f"(c[2]), "+f"(c[3])
        : "r"(a[0]), "r"(a[1]), "r"(a[2]), "r"(a[3]), "r"(b[0]), "r"(b[1]));
}
__device__ __forceinline__ void cp_async16(uint32_t d, const void* s) {
    asm volatile("cp.async.ca.shared.global [%0], [%1], 16;" :: "r"(d), "l"(s) : "memory");
}
__device__ __forceinline__ void cp_commit() {
    asm volatile("cp.async.commit_group;" ::: "memory");
}
__device__ __forceinline__ void cp_wait0() {
    asm volatile("cp.async.wait_group 0;" ::: "memory");
}

// ---------------------------------------------------------------------------
// Weight prep, all 8 weights in ONE launch.
// grid (24, 24, 8), block (32,8); blocks outside a weight's extent exit early.
// ---------------------------------------------------------------------------
struct WJobs {
    const float* W[8];
    __nv_bfloat16* hi[8];
    __nv_bfloat16* lo[8];
    int K[8];
    int N[8];
};

__global__ void wsplit_all_kernel(WJobs jobs)
{
    const int id = blockIdx.z;
    const int K = jobs.K[id], N = jobs.N[id];
    const int kb = blockIdx.y * 32;
    const int nb = blockIdx.x * 32;
    if (kb >= K || nb >= N) return;

    const float* W = jobs.W[id];
    __nv_bfloat16* Whi = jobs.hi[id];
    __nv_bfloat16* Wlo = jobs.lo[id];

    __shared__ float tile[32][33];
    const int tx = threadIdx.x;
    for (int i = threadIdx.y; i < 32; i += 8)
        tile[i][tx] = W[(size_t)(kb + i) * N + nb + tx];
    __syncthreads();
    for (int i = threadIdx.y; i < 32; i += 8) {
        float v = tile[tx][i];               // W[kb+tx][nb+i]
        __nv_bfloat16 h, l;
        split_bf(v, h, l);
        size_t o = (size_t)(nb + i) * K + kb + tx;
        Whi[o] = h;
        Wlo[o] = l;
    }
}

// ---------------------------------------------------------------------------
// bf16x3 HMMA GEMM (unchanged from R4, known good)
// ---------------------------------------------------------------------------
constexpr int GPLANE = 128 * 40 * 2;          // 10240 B per plane
constexpr int GSTAGE = 4 * GPLANE;            // Ahi|Alo|Bhi|Blo = 40960 B
constexpr int GEMM_SMEM = 2 * GSTAGE;         // 81920 B

__global__ __launch_bounds__(256)
void gemm_bf16x3_kernel(const float* __restrict__ A, int lda, int K,
                        const __nv_bfloat16* __restrict__ Whi,
                        const __nv_bfloat16* __restrict__ Wlo,
                        const float* __restrict__ bias,
                        float* __restrict__ C, int ldc)
{
    extern __shared__ char smc[];
    const uint32_t sbase = smem_u32(smc);

    const int tid  = threadIdx.x;
    const int lane = tid & 31;
    const int wid  = tid >> 5;
    const int wm   = wid & 1;
    const int wn   = wid >> 1;
    const int m0 = blockIdx.y * 128;
    const int n0 = blockIdx.x * 128;
    const int KT = K / 32;

    float acc[4][4][4];
    #pragma unroll
    for (int i = 0; i < 4; ++i)
        #pragma unroll
        for (int j = 0; j < 4; ++j)
            #pragma unroll
            for (int k = 0; k < 4; ++k) acc[i][j][k] = 0.f;

    const int arow = tid >> 1;
    const int acol = (tid & 1) * 16;
    const float* aptr = A + (size_t)(m0 + arow) * lda + acol;

    float4 areg[4];

    auto fetch_A = [&](int kt) {
        #pragma unroll
        for (int i = 0; i < 4; ++i)
            areg[i] = *reinterpret_cast<const float4*>(aptr + kt * 32 + i * 4);
    };
    auto store_A = [&](int stage) {
        char* bh = smc + stage * GSTAGE + 0      + arow * 80 + acol * 2;
        char* bl = smc + stage * GSTAGE + GPLANE + arow * 80 + acol * 2;
        #pragma unroll
        for (int i = 0; i < 4; ++i) {
            float4 v = areg[i];
            __nv_bfloat16 h0, h1, h2, h3, l0, l1, l2, l3;
            split_bf(v.x, h0, l0); split_bf(v.y, h1, l1);
            split_bf(v.z, h2, l2); split_bf(v.w, h3, l3);
            uint2 ph = make_uint2(pack_bf2(h0, h1), pack_bf2(h2, h3));
            uint2 pl = make_uint2(pack_bf2(l0, l1), pack_bf2(l2, l3));
            *reinterpret_cast<uint2*>(bh + i * 8) = ph;
            *reinterpret_cast<uint2*>(bl + i * 8) = pl;
        }
    };
    auto load_B = [&](int kt, int stage) {
        #pragma unroll
        for (int j = 0; j < 2; ++j) {
            int cid = tid + 256 * j;
            int row = cid >> 2;
            int k8  = (cid & 3) * 8;
            size_t go = (size_t)(n0 + row) * K + kt * 32 + k8;
            uint32_t dh = sbase + stage * GSTAGE + 2 * GPLANE + row * 80 + k8 * 2;
            uint32_t dl = sbase + stage * GSTAGE + 3 * GPLANE + row * 80 + k8 * 2;
            cp_async16(dh, Whi + go);
            cp_async16(dl, Wlo + go);
        }
    };

    const int la_row = lane & 15;
    const int la_k   = (lane >> 4) * 8;
    const int lb_row = lane & 7;
    const int lb_k   = ((lane >> 3) & 1) * 8;

    auto compute = [&](int stage) {
        const uint32_t st = sbase + stage * GSTAGE;
        #pragma unroll
        for (int ks = 0; ks < 32; ks += 16) {
            uint32_t bh[4][2], bl[4][2];
            #pragma unroll
            for (int nt = 0; nt < 4; ++nt) {
                uint32_t rb = st + 2 * GPLANE
                            + (wn * 32 + nt * 8 + lb_row) * 80 + (ks + lb_k) * 2;
                ldsm_x2(bh[nt], rb);
                ldsm_x2(bl[nt], rb + GPLANE);
            }
            #pragma unroll
            for (int mt = 0; mt < 4; ++mt) {
                uint32_t ra = st
                            + (wm * 64 + mt * 16 + la_row) * 80 + (ks + la_k) * 2;
                uint32_t ah[4], al[4];
                ldsm_x4(ah, ra);
                ldsm_x4(al, ra + GPLANE);
                #pragma unroll
                for (int nt = 0; nt < 4; ++nt) {
                    mma_bf16(acc[mt][nt], ah, bh[nt]);
                    mma_bf16(acc[mt][nt], ah, bl[nt]);
                    mma_bf16(acc[mt][nt], al, bh[nt]);
                }
            }
        }
    };

    fetch_A(0);
    load_B(0, 0);
    cp_commit();
    store_A(0);
    cp_wait0();
    __syncthreads();

    for (int kt = 0; kt < KT; ++kt) {
        const int p = kt & 1;
        const bool more = (kt + 1 < KT);
        if (more) {
            fetch_A(kt + 1);
            load_B(kt + 1, p ^ 1);
            cp_commit();
        }
        compute(p);
        if (more) {
            store_A(p ^ 1);
            cp_wait0();
        }
        __syncthreads();
    }

    #pragma unroll
    for (int mt = 0; mt < 4; ++mt) {
        int r0 = m0 + wm * 64 + mt * 16 + (lane >> 2);
        #pragma unroll
        for (int nt = 0; nt < 4; ++nt) {
            int col = n0 + wn * 32 + nt * 8 + (lane & 3) * 2;
            float2 bv = *reinterpret_cast<const float2*>(bias + col);
            float2 o0 = make_float2(acc[mt][nt][0] + bv.x, acc[mt][nt][1] + bv.y);
            float2 o1 = make_float2(acc[mt][nt][2] + bv.x, acc[mt][nt][3] + bv.y);
            *reinterpret_cast<float2*>(C + (size_t)r0 * ldc + col) = o0;
            *reinterpret_cast<float2*>(C + (size_t)(r0 + 8) * ldc + col) = o1;
        }
    }
}

// ---------------------------------------------------------------------------
// Tensor-core flash attention (bf16x3), causal, head_dim=64.
// Q tile 128 rows (8 warps x 16), KV tile 64.
// SMEM bf16 planes (pitch 72 elems = 144 B):
//   Qh @0, Ql @18432, Kh @36864, Kl @46080, Vth @55296, Vtl @64512  (73728 B)
// V stored transposed [d][key] so PV B-fragments use plain ldmatrix.
// ---------------------------------------------------------------------------
constexpr int AP = 72;
constexpr int ATT_SMEM = 73728;
constexpr int QH_B = 0,     QL_B = 18432;
constexpr int KH_B = 36864, KL_B = 46080;
constexpr int VH_B = 55296, VL_B = 64512;

__global__ __launch_bounds__(256)
void attn_tc_kernel(const float* __restrict__ qkv_all,
                    float* __restrict__ attn_out)
{
    extern __shared__ char smb[];
    const uint32_t S = smem_u32(smb);

    const int tid  = threadIdx.x;
    const int lane = tid & 31;
    const int w    = tid >> 5;
    const int qt = blockIdx.x;
    const int bh = blockIdx.y;
    const int g  = blockIdx.z;
    const int b  = bh >> 2;
    const int h  = bh & 3;
    const int q0 = qt * 128;

    const float* base = qkv_all + (size_t)g * MROWS * DIM + (size_t)b * SEQ * DIM;
    const int qo = h * HDIM;
    const int ko = GDIM + h * HDIM;
    const int vo = 2 * GDIM + h * HDIM;

    // ---- stage Q: scale by 1/8, split hi/lo ----
    {
        const int row = tid >> 1;             // 0..127
        const int c0  = (tid & 1) * 32;
        const float* src = base + (size_t)(q0 + row) * DIM + qo + c0;
        char* dh = smb + QH_B + (row * AP + c0) * 2;
        char* dl = smb + QL_B + (row * AP + c0) * 2;
        #pragma unroll
        for (int i = 0; i < 8; ++i) {
            float4 v = *reinterpret_cast<const float4*>(src + i * 4);
            v.x *= 0.125f; v.y *= 0.125f; v.z *= 0.125f; v.w *= 0.125f;
            __nv_bfloat16 h0, h1, h2, h3, l0, l1, l2, l3;
            split_bf(v.x, h0, l0); split_bf(v.y, h1, l1);
            split_bf(v.z, h2, l2); split_bf(v.w, h3, l3);
            *reinterpret_cast<uint2*>(dh + i * 8) =
                make_uint2(pack_bf2(h0, h1), pack_bf2(h2, h3));
            *reinterpret_cast<uint2*>(dl + i * 8) =
                make_uint2(pack_bf2(l0, l1), pack_bf2(l2, l3));
        }
    }
    __syncthreads();

    // ---- Q A-fragments held in registers for the whole KV loop ----
    uint32_t aqh[4][4], aql[4][4];
    {
        const int ar = w * 16 + (lane & 15);
        const int ak = (lane >> 4) * 8;
        #pragma unroll
        for (int ks = 0; ks < 4; ++ks) {
            uint32_t a = S + QH_B + (ar * AP + ks * 16 + ak) * 2;
            ldsm_x4(aqh[ks], a);
            ldsm_x4(aql[ks], a + (QL_B - QH_B));
        }
    }

    float m_[2] = {-1e30f, -1e30f};
    float l_[2] = {0.f, 0.f};
    float oacc[8][4];
    #pragma unroll
    for (int j = 0; j < 8; ++j)
        #pragma unroll
        for (int r = 0; r < 4; ++r) oacc[j][r] = 0.f;

    const int jt_max = (q0 + 127) >> 6;
    for (int jt = 0; jt <= jt_max; ++jt) {
        const int j0 = jt * 64;
        __syncthreads();   // previous iteration's PV reads done

        // ---- stage K (K-major) and V (transposed), split hi/lo ----
        {
            const int row = tid >> 2;          // 0..63 (key index)
            const int c0  = (tid & 3) * 16;    // d offset
            const float* ksrc = base + (size_t)(j0 + row) * DIM + ko + c0;
            const float* vsrc = base + (size_t)(j0 + row) * DIM + vo + c0;
            char* kdh = smb + KH_B + (row * AP + c0) * 2;
            char* kdl = smb + KL_B + (row * AP + c0) * 2;
            #pragma unroll
            for (int i = 0; i < 4; ++i) {
                float4 kv = *reinterpret_cast<const float4*>(ksrc + i * 4);
                __nv_bfloat16 h0, h1, h2, h3, l0, l1, l2, l3;
                split_bf(kv.x, h0, l0); split_bf(kv.y, h1, l1);
                split_bf(kv.z, h2, l2); split_bf(kv.w, h3, l3);
                *reinterpret_cast<uint2*>(kdh + i * 8) =
                    make_uint2(pack_bf2(h0, h1), pack_bf2(h2, h3));
                *reinterpret_cast<uint2*>(kdl + i * 8) =
                    make_uint2(pack_bf2(l0, l1), pack_bf2(l2, l3));

                float4 vv = *reinterpret_cast<const float4*>(vsrc + i * 4);
                const float vals[4] = {vv.x, vv.y, vv.z, vv.w};
                #pragma unroll
                for (int e = 0; e < 4; ++e) {
                    __nv_bfloat16 hh, ll;
                    split_bf(vals[e], hh, ll);
                    const int col = c0 + i * 4 + e;  // d index
                    *reinterpret_cast<__nv_bfloat16*>(
                        smb + VH_B + (col * AP + row) * 2) = hh;
                    *reinterpret_cast<__nv_bfloat16*>(
                        smb + VL_B + (col * AP + row) * 2) = ll;
                }
            }
        }
        __syncthreads();

        // ---- per-warp skip of fully masked tiles ----
        if (j0 > q0 + w * 16 + 15) continue;

        // ---- S = Qs K^T (bf16x3) ----
        float sacc[8][4];
        #pragma unroll
        for (int j = 0; j < 8; ++j)
            #pragma unroll
            for (int r = 0; r < 4; ++r) sacc[j][r] = 0.f;

        {
            const int br = (lane & 7) + ((lane >> 4) << 3);
            const int bkl = ((lane >> 3) & 1) * 8;
            #pragma unroll
            for (int ks = 0; ks < 4; ++ks) {
                uint32_t bhf[4][4], blf[4][4];
                #pragma unroll
                for (int np = 0; np < 4; ++np) {
                    uint32_t a = S + KH_B
                               + ((np * 16 + br) * AP + ks * 16 + bkl) * 2;
                    ldsm_x4(bhf[np], a);
                    ldsm_x4(blf[np], a + (KL_B - KH_B));
                }
                #pragma unroll
                for (int np = 0; np < 4; ++np) {
                    mma_bf16(sacc[2 * np],     aqh[ks], &bhf[np][0]);
                    mma_bf16(sacc[2 * np + 1], aqh[ks], &bhf[np][2]);
                }
                #pragma unroll
                for (int np = 0; np < 4; ++np) {
                    mma_bf16(sacc[2 * np],     aqh[ks], &blf[np][0]);
                    mma_bf16(sacc[2 * np + 1], aqh[ks], &blf[np][2]);
                }
                #pragma unroll
                for (int np = 0; np < 4; ++np) {
                    mma_bf16(sacc[2 * np],     aql[ks], &bhf[np][0]);
                    mma_bf16(sacc[2 * np + 1], aql[ks], &bhf[np][2]);
                }
            }
        }

        // ---- causal mask (partial tiles only) ----
        const int rbase = q0 + w * 16 + (lane >> 2);
        const int cbase = (lane & 3) * 2;
        if (j0 + 63 > q0 + w * 16) {
            #pragma unroll
            for (int j = 0; j < 8; ++j)
                #pragma unroll
                for (int rw = 0; rw < 2; ++rw)
                    #pragma unroll
                    for (int c = 0; c < 2; ++c)
                        if (j0 + j * 8 + cbase + c > rbase + rw * 8)
                            sacc[j][rw * 2 + c] = -1e30f;
        }

        // ---- online softmax ----
        #pragma unroll
        for (int rw = 0; rw < 2; ++rw) {
            float rm = -1e30f;
            #pragma unroll
            for (int j = 0; j < 8; ++j) {
                rm = fmaxf(rm, sacc[j][rw * 2]);
                rm = fmaxf(rm, sacc[j][rw * 2 + 1]);
            }
            rm = fmaxf(rm, __shfl_xor_sync(0xffffffffu, rm, 1));
            rm = fmaxf(rm, __shfl_xor_sync(0xffffffffu, rm, 2));
            const float mnew  = fmaxf(m_[rw], rm);
            const float alpha = __expf(m_[rw] - mnew);
            m_[rw] = mnew;
            float rs = 0.f;
            #pragma unroll
            for (int j = 0; j < 8; ++j) {
                float p0 = __expf(sacc[j][rw * 2]     - mnew);
                float p1 = __expf(sacc[j][rw * 2 + 1] - mnew);
                sacc[j][rw * 2]     = p0;
                sacc[j][rw * 2 + 1] = p1;
                rs += p0 + p1;
            }
            rs += __shfl_xor_sync(0xffffffffu, rs, 1);
            rs += __shfl_xor_sync(0xffffffffu, rs, 2);
            l_[rw] = l_[rw] * alpha + rs;
            #pragma unroll
            for (int j = 0; j < 8; ++j) {
                oacc[j][rw * 2]     *= alpha;
                oacc[j][rw * 2 + 1] *= alpha;
            }
        }

        // ---- P: C-fragments -> A-fragments in registers, split hi/lo ----
        uint32_t ph4[4][4], pl4[4][4];
        #pragma unroll
        for (int u = 0; u < 4; ++u) {
            ph4[u][0] = packsplit(sacc[2 * u][0],     sacc[2 * u][1],     pl4[u][0]);
            ph4[u][1] = packsplit(sacc[2 * u][2],     sacc[2 * u][3],     pl4[u][1]);
            ph4[u][2] = packsplit(sacc[2 * u + 1][0], sacc[2 * u + 1][1], pl4[u][2]);
            ph4[u][3] = packsplit(sacc[2 * u + 1][2], sacc[2 * u + 1][3], pl4[u][3]);
        }

        // ---- O += P V (bf16x3), V^T staged [d][key] ----
        {
            const int vr = (lane & 7) + ((lane >> 4) << 3);
            const int vkl = ((lane >> 3) & 1) * 8;
            #pragma unroll
            for (int u = 0; u < 4; ++u) {
                uint32_t bvh[4][4], bvl[4][4];
                #pragma unroll
                for (int np = 0; np < 4; ++np) {
                    uint32_t a = S + VH_B
                               + ((np * 16 + vr) * AP + u * 16 + vkl) * 2;
                    ldsm_x4(bvh[np], a);
                    ldsm_x4(bvl[np], a + (VL_B - VH_B));
                }
                #pragma unroll
                for (int np = 0; np < 4; ++np) {
                    mma_bf16(oacc[2 * np],     ph4[u], &bvh[np][0]);
                    mma_bf16(oacc[2 * np + 1], ph4[u], &bvh[np][2]);
                }
                #pragma unroll
                for (int np = 0; np < 4; ++np) {
                    mma_bf16(oacc[2 * np],     ph4[u], &bvl[np][0]);
                    mma_bf16(oacc[2 * np + 1], ph4[u], &bvl[np][2]);
                }
                #pragma unroll
                for (int np = 0; np < 4; ++np) {
                    mma_bf16(oacc[2 * np],     pl4[u], &bvh[np][0]);
                    mma_bf16(oacc[2 * np + 1], pl4[u], &bvh[np][2]);
                }
            }
        }
    }

    // ---- finalize + write ----
    #pragma unroll
    for (int rw = 0; rw < 2; ++rw) {
        const float inv = 1.0f / l_[rw];
        const size_t row = (size_t)b * SEQ + q0 + w * 16 + (lane >> 2) + rw * 8;
        float* orow = attn_out + row * DIM + g * GDIM + h * HDIM + (lane & 3) * 2;
        #pragma unroll
        for (int j = 0; j < 8; ++j) {
            float2 o = make_float2(oacc[j][rw * 2] * inv,
                                   oacc[j][rw * 2 + 1] * inv);
            *reinterpret_cast<float2*>(orow + j * 8) = o;
        }
    }
}

// ---------------------------------------------------------------------------
// PDE kernels (unchanged, known good)
// ---------------------------------------------------------------------------
__global__ void pde_sg_kernel(float* __restrict__ u)
{
    const int b = blockIdx.x >> 8;
    const int c = blockIdx.x & 255;
    float* col = u + (size_t)b * SEQ * DIM + c;
    __shared__ float su[SEQ], sw[SEQ];
    const int tid = threadIdx.x;
    for (int t = tid; t < SEQ; t += 256) { su[t] = col[(size_t)t * DIM]; sw[t] = 0.f; }
    __syncthreads();
    for (int step = 0; step < 3; ++step) {
        float dw[8];
        #pragma unroll
        for (int i = 0; i < 8; ++i) {
            int t = tid + i * 256;
            float um = (t > 0)       ? su[t - 1] : 0.f;
            float up = (t < SEQ - 1) ? su[t + 1] : 0.f;
            dw[i] = DT_F * ((um - 2.f * su[t] + up) - sinf(su[t]));
        }
        __syncthreads();
        #pragma unroll
        for (int i = 0; i < 8; ++i) {
            int t = tid + i * 256;
            sw[t] += dw[i];
            su[t] += DT_F * sw[t];
        }
        __syncthreads();
    }
    for (int t = tid; t < SEQ; t += 256) col[(size_t)t * DIM] = su[t];
}

__global__ void pde_kdv_kernel(float* __restrict__ u)
{
    const int b = blockIdx.x >> 8;
    const int c = blockIdx.x & 255;
    float* col = u + (size_t)b * SEQ * DIM + c;
    __shared__ float su[SEQ];
    const int tid = threadIdx.x;
    for (int t = tid; t < SEQ; t += 256) su[t] = col[(size_t)t * DIM];
    __syncthreads();
    for (int step = 0; step < 3; ++step) {
        float du[8];
        #pragma unroll
        for (int i = 0; i < 8; ++i) {
            int t = tid + i * 256;
            float um2 = (t > 1)       ? su[t - 2] : 0.f;
            float um1 = (t > 0)       ? su[t - 1] : 0.f;
            float up1 = (t < SEQ - 1) ? su[t + 1] : 0.f;
            float up2 = (t < SEQ - 2) ? su[t + 2] : 0.f;
            float d1 = 0.5f * (up1 - um1);
            float d3 = 0.5f * (up2 - 2.f * up1 + 2.f * um1 - um2);
            du[i] = DT_F * (-6.f * su[t] * d1 - d3);
        }
        __syncthreads();
        #pragma unroll
        for (int i = 0; i < 8; ++i) {
            int t = tid + i * 256;
            su[t] += du[i];
        }
        __syncthreads();
    }
    for (int t = tid; t < SEQ; t += 256) col[(size_t)t * DIM] = su[t];
}

__global__ void pde_hj_kernel(float* __restrict__ u)
{
    const int b = blockIdx.x >> 8;
    const int c = blockIdx.x & 255;
    float* col = u + (size_t)b * SEQ * DIM + c;
    __shared__ float su[SEQ], sw[SEQ], sf[SEQ];
    const int tid = threadIdx.x;
    for (int t = tid; t < SEQ; t += 256) { su[t] = col[(size_t)t * DIM]; sw[t] = 0.f; }
    __syncthreads();
    for (int step = 0; step < 3; ++step) {
        #pragma unroll
        for (int i = 0; i < 8; ++i) {
            int t = tid + i * 256;
            float v = su[t];
            sf[t] = v - v * v + v * v * v;
        }
        __syncthreads();
        float dw[8];
        #pragma unroll
        for (int i = 0; i < 8; ++i) {
            int t = tid + i * 256;
            float fm  = (t > 0)       ? sf[t - 1] : 0.f;
            float fp  = (t < SEQ - 1) ? sf[t + 1] : 0.f;
            float d2f = fm - 2.f * sf[t] + fp;
            float um2 = (t > 1)       ? su[t - 2] : 0.f;
            float um1 = (t > 0)       ? su[t - 1] : 0.f;
            float up1 = (t < SEQ - 1) ? su[t + 1] : 0.f;
            float up2 = (t < SEQ - 2) ? su[t + 2] : 0.f;
            float d4  = um2 - 4.f * um1 + 6.f * su[t] - 4.f * up1 + up2;
            dw[i] = DT_F * (d2f - HJ_HF * d4);
        }
        __syncthreads();
        #pragma unroll
        for (int i = 0; i < 8; ++i) {
            int t = tid + i * 256;
            sw[t] += dw[i];
            su[t] += DT_F * sw[t];
        }
        __syncthreads();
    }
    for (int t = tid; t < SEQ; t += 256) col[(size_t)t * DIM] = su[t];
}

// ---------------------------------------------------------------------------
// Launch
// ---------------------------------------------------------------------------
extern "C" void kernel_launch(void* const* d_in, const int* in_sizes, int n_in,
                              void* d_out, int out_size)
{
    const float* x      = (const float*)d_in[0];
    const float* in_w   = (const float*)d_in[1];
    const float* in_b   = (const float*)d_in[2];
    const float* qkv_w[3] = {(const float*)d_in[3],  (const float*)d_in[7],  (const float*)d_in[11]};
    const float* qkv_b[3] = {(const float*)d_in[4],  (const float*)d_in[8],  (const float*)d_in[12]};
    const float* ow[3]    = {(const float*)d_in[5],  (const float*)d_in[9],  (const float*)d_in[13]};
    const float* ob[3]    = {(const float*)d_in[6],  (const float*)d_in[10], (const float*)d_in[14]};
    const float* out_w  = (const float*)d_in[15];
    const float* out_b  = (const float*)d_in[16];
    float* out = (float*)d_out;

    float *h, *qkv, *attn, *u;
    __nv_bfloat16 *whi, *wlo;
    cudaGetSymbolAddress((void**)&h,    g_h);
    cudaGetSymbolAddress((void**)&qkv,  g_qkv);
    cudaGetSymbolAddress((void**)&attn, g_attn);
    cudaGetSymbolAddress((void**)&u,    g_u);
    cudaGetSymbolAddress((void**)&whi,  g_whi);
    cudaGetSymbolAddress((void**)&wlo,  g_wlo);

    cudaFuncSetAttribute(attn_tc_kernel,
                         cudaFuncAttributeMaxDynamicSharedMemorySize, ATT_SMEM);
    cudaFuncSetAttribute(gemm_bf16x3_kernel,
                         cudaFuncAttributeMaxDynamicSharedMemorySize, GEMM_SMEM);

    // ---- weight prep: single launch for all 8 weights ----
    WJobs jobs;
    jobs.W[0] = in_w;  jobs.hi[0] = whi + WT_IN;  jobs.lo[0] = wlo + WT_IN;
    jobs.K[0] = 768;   jobs.N[0] = 768;
    for (int g = 0; g < 3; ++g) {
        jobs.W[1 + g]  = qkv_w[g];
        jobs.hi[1 + g] = whi + WT_QKV0 + g * 768 * 256;
        jobs.lo[1 + g] = wlo + WT_QKV0 + g * 768 * 256;
        jobs.K[1 + g]  = 256; jobs.N[1 + g] = 768;
        jobs.W[4 + g]  = ow[g];
        jobs.hi[4 + g] = whi + WT_OW0 + g * 256 * 256;
        jobs.lo[4 + g] = wlo + WT_OW0 + g * 256 * 256;
        jobs.K[4 + g]  = 256; jobs.N[4 + g] = 256;
    }
    jobs.W[7] = out_w; jobs.hi[7] = whi + WT_OUT; jobs.lo[7] = wlo + WT_OUT;
    jobs.K[7] = 768;   jobs.N[7] = 768;
    wsplit_all_kernel<<<dim3(24, 24, 8), dim3(32, 8)>>>(jobs);

    // 1) h = x @ in_w + in_b
    gemm_bf16x3_kernel<<<dim3(768 / 128, MROWS / 128), 256, GEMM_SMEM>>>(
        x, DIM, 768, whi + WT_IN, wlo + WT_IN, in_b, h, DIM);

    // 2) per-group qkv
    for (int g = 0; g < 3; ++g)
        gemm_bf16x3_kernel<<<dim3(768 / 128, MROWS / 128), 256, GEMM_SMEM>>>(
            h + g * GDIM, DIM, 256,
            whi + WT_QKV0 + g * 768 * 256, wlo + WT_QKV0 + g * 768 * 256,
            qkv_b[g], qkv + (size_t)g * MROWS * DIM, DIM);

    // 3) causal attention (tensor cores)
    attn_tc_kernel<<<dim3(SEQ / 128, BATCH * 4, 3), 256, ATT_SMEM>>>(qkv, attn);

    // 4) per-group out projection
    for (int g = 0; g < 3; ++g)
        gemm_bf16x3_kernel<<<dim3(256 / 128, MROWS / 128), 256, GEMM_SMEM>>>(
            attn + g * GDIM, DIM, 256,
            whi + WT_OW0 + g * 256 * 256, wlo + WT_OW0 + g * 256 * 256,
            ob[g], u + g * GDIM, DIM);

    // 5) PDE evolutions
    pde_sg_kernel <<<BATCH * GDIM, 256>>>(u + 0 * GDIM);
    pde_kdv_kernel<<<BATCH * GDIM, 256>>>(u + 1 * GDIM);
    pde_hj_kernel <<<BATCH * GDIM, 256>>>(u + 2 * GDIM);

    // 6) out = u @ out_w + out_b
    gemm_bf16x3_kernel<<<dim3(768 / 128, MROWS / 128), 256, GEMM_SMEM>>>(
        u, DIM, 768, whi + WT_OUT, wlo + WT_OUT, out_b, out, DIM);
}

// round 6
// speedup vs baseline: 2.2925x; 1.1026x over previous
#include <cuda_runtime.h>
#include <cuda_bf16.h>
#include <math.h>
#include <stdint.h>

// ---------------------------------------------------------------------------
// Problem constants
// ---------------------------------------------------------------------------
constexpr int BATCH = 4;
constexpr int SEQ   = 2048;
constexpr int DIM   = 768;
constexpr int GDIM  = 256;
constexpr int HDIM  = 64;
constexpr int MROWS = BATCH * SEQ;   // 8192
constexpr float DT_F  = 0.05f;
constexpr float HJ_HF = 0.05f;
constexpr int MD = MROWS * DIM;

// ---------------------------------------------------------------------------
// Device scratch (no cudaMalloc allowed)
// ---------------------------------------------------------------------------
__device__ __nv_bfloat16 g_xh[MD],  g_xl[MD];      // split input x
__device__ __nv_bfloat16 g_hh[MD],  g_hl[MD];      // split h
__device__ __nv_bfloat16 g_qh[3 * MD], g_ql[3 * MD]; // split qkv per group
__device__ __nv_bfloat16 g_ah[MD],  g_al[MD];      // split attention out
__device__ __nv_bfloat16 g_uh[MD],  g_ul[MD];      // split post-PDE u
__device__ float g_u[MD];                          // fp32 u (PDE state)

constexpr int WT_IN   = 0;
constexpr int WT_QKV0 = WT_IN   + 768 * 768;
constexpr int WT_OW0  = WT_QKV0 + 3 * 768 * 256;
constexpr int WT_OUT  = WT_OW0  + 3 * 256 * 256;
constexpr int WT_TOTAL = WT_OUT + 768 * 768;
__device__ __nv_bfloat16 g_whi[WT_TOTAL];
__device__ __nv_bfloat16 g_wlo[WT_TOTAL];

// ---------------------------------------------------------------------------
// Helpers
// ---------------------------------------------------------------------------
__device__ __forceinline__ uint32_t smem_u32(const void* p) {
    uint32_t a;
    asm("{ .reg .u64 t; cvta.to.shared.u64 t, %1; cvt.u32.u64 %0, t; }"
        : "=r"(a) : "l"(p));
    return a;
}
__device__ __forceinline__ void split_bf(float v, __nv_bfloat16& h, __nv_bfloat16& l) {
    h = __float2bfloat16_rn(v);
    l = __float2bfloat16_rn(v - __bfloat162float(h));
}
__device__ __forceinline__ uint32_t pack_bf2(__nv_bfloat16 a, __nv_bfloat16 b) {
    uint16_t ua = *reinterpret_cast<uint16_t*>(&a);
    uint16_t ub = *reinterpret_cast<uint16_t*>(&b);
    return (uint32_t)ua | ((uint32_t)ub << 16);
}
__device__ __forceinline__ uint32_t packsplit(float a, float b, uint32_t& lo) {
    __nv_bfloat16 ha = __float2bfloat16_rn(a), hb = __float2bfloat16_rn(b);
    __nv_bfloat16 la = __float2bfloat16_rn(a - __bfloat162float(ha));
    __nv_bfloat16 lb = __float2bfloat16_rn(b - __bfloat162float(hb));
    lo = pack_bf2(la, lb);
    return pack_bf2(ha, hb);
}
__device__ __forceinline__ void ldsm_x4(uint32_t* r, uint32_t a) {
    asm volatile("ldmatrix.sync.aligned.m8n8.x4.shared.b16 {%0,%1,%2,%3}, [%4];"
        : "=r"(r[0]), "=r"(r[1]), "=r"(r[2]), "=r"(r[3]) : "r"(a));
}
__device__ __forceinline__ void ldsm_x4t(uint32_t* r, uint32_t a) {
    asm volatile("ldmatrix.sync.aligned.m8n8.x4.trans.shared.b16 {%0,%1,%2,%3}, [%4];"
        : "=r"(r[0]), "=r"(r[1]), "=r"(r[2]), "=r"(r[3]) : "r"(a));
}
__device__ __forceinline__ void ldsm_x2(uint32_t* r, uint32_t a) {
    asm volatile("ldmatrix.sync.aligned.m8n8.x2.shared.b16 {%0,%1}, [%2];"
        : "=r"(r[0]), "=r"(r[1]) : "r"(a));
}
__device__ __forceinline__ void mma_bf16(float* c, const uint32_t* a, const uint32_t* b) {
    asm volatile("mma.sync.aligned.m16n8k16.row.col.f32.bf16.bf16.f32 "
        "{%0,%1,%2,%3}, {%4,%5,%6,%7}, {%8,%9}, {%0,%1,%2,%3};"
        : "+f"(c[0]), "+f"(c[1]), "+f"(c[2]), "+f"(c[3])
        : "r"(a[0]), "r"(a[1]), "r"(a[2]), "r"(a[3]), "r"(b[0]), "r"(b[1]));
}
__device__ __forceinline__ void cp_async16(uint32_t d, const void* s) {
    asm volatile("cp.async.ca.shared.global [%0], [%1], 16;" :: "r"(d), "l"(s) : "memory");
}
__device__ __forceinline__ void cp_commit() {
    asm volatile("cp.async.commit_group;" ::: "memory");
}
__device__ __forceinline__ void cp_wait0() {
    asm volatile("cp.async.wait_group 0;" ::: "memory");
}
__device__ __forceinline__ void cp_wait1() {
    asm volatile("cp.async.wait_group 1;" ::: "memory");
}

// ---------------------------------------------------------------------------
// Weight prep: all 8 weights in one launch.
// ---------------------------------------------------------------------------
struct WJobs {
    const float* W[8];
    __nv_bfloat16* hi[8];
    __nv_bfloat16* lo[8];
    int K[8];
    int N[8];
};

__global__ void wsplit_all_kernel(WJobs jobs)
{
    const int id = blockIdx.z;
    const int K = jobs.K[id], N = jobs.N[id];
    const int kb = blockIdx.y * 32;
    const int nb = blockIdx.x * 32;
    if (kb >= K || nb >= N) return;

    const float* W = jobs.W[id];
    __nv_bfloat16* Whi = jobs.hi[id];
    __nv_bfloat16* Wlo = jobs.lo[id];

    __shared__ float tile[32][33];
    const int tx = threadIdx.x;
    for (int i = threadIdx.y; i < 32; i += 8)
        tile[i][tx] = W[(size_t)(kb + i) * N + nb + tx];
    __syncthreads();
    for (int i = threadIdx.y; i < 32; i += 8) {
        float v = tile[tx][i];
        __nv_bfloat16 h, l;
        split_bf(v, h, l);
        size_t o = (size_t)(nb + i) * K + kb + tx;
        Whi[o] = h;
        Wlo[o] = l;
    }
}

// ---------------------------------------------------------------------------
// Activation split: fp32 -> hi/lo bf16 planes (for the network input x).
// ---------------------------------------------------------------------------
__global__ void asplit_kernel(const float* __restrict__ A,
                              __nv_bfloat16* __restrict__ hi,
                              __nv_bfloat16* __restrict__ lo, int n)
{
    int i = (blockIdx.x * 256 + threadIdx.x) * 4;
    if (i >= n) return;
    float4 v = *reinterpret_cast<const float4*>(A + i);
    __nv_bfloat16 h0, h1, h2, h3, l0, l1, l2, l3;
    split_bf(v.x, h0, l0); split_bf(v.y, h1, l1);
    split_bf(v.z, h2, l2); split_bf(v.w, h3, l3);
    *reinterpret_cast<uint2*>(hi + i) = make_uint2(pack_bf2(h0, h1), pack_bf2(h2, h3));
    *reinterpret_cast<uint2*>(lo + i) = make_uint2(pack_bf2(l0, l1), pack_bf2(l2, l3));
}

// ---------------------------------------------------------------------------
// bf16x3 HMMA GEMM, pre-split A planes, all-cp.async, fused over blockIdx.z.
// Block 128x128x32, 256 threads (8 warps 2x4), 2-stage pipeline.
// OUT_SPLIT: write hi/lo bf16 planes; else fp32.
// ---------------------------------------------------------------------------
constexpr int GPLANE = 128 * 80;              // 10240 B per plane (pitch 80B)
constexpr int GSTAGE = 4 * GPLANE;            // Ah|Al|Bh|Bl
constexpr int GEMM_SMEM = 2 * GSTAGE;         // 81920 B

struct GemmArgs {
    const __nv_bfloat16* Ah[3];
    const __nv_bfloat16* Al[3];
    int lda, K;
    const __nv_bfloat16* Bh[3];
    const __nv_bfloat16* Bl[3];
    const float* bias[3];
    float* Cf[3];
    __nv_bfloat16* Ch[3];
    __nv_bfloat16* Cl[3];
    int ldc;
};

template<bool OUT_SPLIT>
__global__ __launch_bounds__(256)
void gemm_pp_kernel(GemmArgs p)
{
    extern __shared__ char smc[];
    const uint32_t sbase = smem_u32(smc);

    const int tid  = threadIdx.x;
    const int lane = tid & 31;
    const int wid  = tid >> 5;
    const int wm   = wid & 1;
    const int wn   = wid >> 1;
    const int m0 = blockIdx.y * 128;
    const int n0 = blockIdx.x * 128;
    const int z  = blockIdx.z;
    const int KT = p.K / 32;

    const __nv_bfloat16* Ah = p.Ah[z];
    const __nv_bfloat16* Al = p.Al[z];
    const __nv_bfloat16* Bh = p.Bh[z];
    const __nv_bfloat16* Bl = p.Bl[z];

    float acc[4][4][4];
    #pragma unroll
    for (int i = 0; i < 4; ++i)
        #pragma unroll
        for (int j = 0; j < 4; ++j)
            #pragma unroll
            for (int k = 0; k < 4; ++k) acc[i][j][k] = 0.f;

    // stage: 4 planes x 128 rows x 4 chunks(16B) = 2048 chunks; 8 per thread
    auto stage = [&](int kt, int s) {
        #pragma unroll
        for (int j = 0; j < 8; ++j) {
            int cid = tid + 256 * j;
            int plane = cid >> 9;
            int idx = cid & 511;
            int row = idx >> 2;
            int ch  = idx & 3;
            const __nv_bfloat16* src;
            if      (plane == 0) src = Ah + (size_t)(m0 + row) * p.lda + kt * 32 + ch * 8;
            else if (plane == 1) src = Al + (size_t)(m0 + row) * p.lda + kt * 32 + ch * 8;
            else if (plane == 2) src = Bh + (size_t)(n0 + row) * p.K + kt * 32 + ch * 8;
            else                 src = Bl + (size_t)(n0 + row) * p.K + kt * 32 + ch * 8;
            cp_async16(sbase + s * GSTAGE + plane * GPLANE + row * 80 + ch * 16, src);
        }
    };

    const int la_row = lane & 15;
    const int la_k   = (lane >> 4) * 8;
    const int lb_row = lane & 7;
    const int lb_k   = ((lane >> 3) & 1) * 8;

    auto compute = [&](int s) {
        const uint32_t st = sbase + s * GSTAGE;
        #pragma unroll
        for (int ks = 0; ks < 32; ks += 16) {
            uint32_t bh[4][2], bl[4][2];
            #pragma unroll
            for (int nt = 0; nt < 4; ++nt) {
                uint32_t rb = st + 2 * GPLANE
                            + (wn * 32 + nt * 8 + lb_row) * 80 + (ks + lb_k) * 2;
                ldsm_x2(bh[nt], rb);
                ldsm_x2(bl[nt], rb + GPLANE);
            }
            #pragma unroll
            for (int mt = 0; mt < 4; ++mt) {
                uint32_t ra = st
                            + (wm * 64 + mt * 16 + la_row) * 80 + (ks + la_k) * 2;
                uint32_t ah[4], al[4];
                ldsm_x4(ah, ra);
                ldsm_x4(al, ra + GPLANE);
                #pragma unroll
                for (int nt = 0; nt < 4; ++nt) {
                    mma_bf16(acc[mt][nt], ah, bh[nt]);
                    mma_bf16(acc[mt][nt], ah, bl[nt]);
                    mma_bf16(acc[mt][nt], al, bh[nt]);
                }
            }
        }
    };

    stage(0, 0);
    cp_commit();
    for (int kt = 0; kt < KT; ++kt) {
        const int s = kt & 1;
        const bool more = kt + 1 < KT;
        if (more) {
            stage(kt + 1, s ^ 1);
            cp_commit();
            cp_wait1();
        } else {
            cp_wait0();
        }
        __syncthreads();
        compute(s);
        __syncthreads();
    }

    #pragma unroll
    for (int mt = 0; mt < 4; ++mt) {
        int r0 = m0 + wm * 64 + mt * 16 + (lane >> 2);
        #pragma unroll
        for (int nt = 0; nt < 4; ++nt) {
            int col = n0 + wn * 32 + nt * 8 + (lane & 3) * 2;
            float2 bv = *reinterpret_cast<const float2*>(p.bias[z] + col);
            float c00 = acc[mt][nt][0] + bv.x, c01 = acc[mt][nt][1] + bv.y;
            float c10 = acc[mt][nt][2] + bv.x, c11 = acc[mt][nt][3] + bv.y;
            if (OUT_SPLIT) {
                uint32_t lo0, lo1;
                uint32_t hi0 = packsplit(c00, c01, lo0);
                uint32_t hi1 = packsplit(c10, c11, lo1);
                __nv_bfloat16* Ch = p.Ch[z];
                __nv_bfloat16* Cl = p.Cl[z];
                *reinterpret_cast<uint32_t*>(Ch + (size_t)r0 * p.ldc + col) = hi0;
                *reinterpret_cast<uint32_t*>(Cl + (size_t)r0 * p.ldc + col) = lo0;
                *reinterpret_cast<uint32_t*>(Ch + (size_t)(r0 + 8) * p.ldc + col) = hi1;
                *reinterpret_cast<uint32_t*>(Cl + (size_t)(r0 + 8) * p.ldc + col) = lo1;
            } else {
                float* Cf = p.Cf[z];
                *reinterpret_cast<float2*>(Cf + (size_t)r0 * p.ldc + col) =
                    make_float2(c00, c01);
                *reinterpret_cast<float2*>(Cf + (size_t)(r0 + 8) * p.ldc + col) =
                    make_float2(c10, c11);
            }
        }
    }
}

// ---------------------------------------------------------------------------
// Tensor-core flash attention, pre-split planes in/out, double-buffered KV.
// Q tile 128 (8 warps x 16 rows), KV tile 64. head_dim=64, scale applied to S.
// SMEM (bf16, pitch 72 elems = 144B):
//   Qh @0 (18432), Ql @18432
//   KV stage s @36864 + s*36864: Kh +0, Kl +9216, Vh +18432, Vl +27648
// V kept [key][d]; PV B-fragments via ldmatrix.x4.trans.
// ---------------------------------------------------------------------------
constexpr int AP = 72;
constexpr int AQH = 0, AQL = 18432;
constexpr int AKV0 = 36864, AKVS = 36864;
constexpr int ATT_SMEM = AKV0 + 2 * AKVS;   // 110592

__global__ __launch_bounds__(256)
void attn_tc_kernel(const __nv_bfloat16* __restrict__ qkvh,
                    const __nv_bfloat16* __restrict__ qkvl,
                    __nv_bfloat16* __restrict__ attnh,
                    __nv_bfloat16* __restrict__ attnl)
{
    extern __shared__ char smb[];
    const uint32_t S = smem_u32(smb);

    const int tid  = threadIdx.x;
    const int lane = tid & 31;
    const int w    = tid >> 5;
    const int qt = gridDim.x - 1 - blockIdx.x;   // heavy blocks first
    const int bh = blockIdx.y;
    const int g  = blockIdx.z;
    const int b  = bh >> 2;
    const int h  = bh & 3;
    const int q0 = qt * 128;

    const size_t gb = (size_t)g * MROWS * DIM + (size_t)b * SEQ * DIM;
    const __nv_bfloat16* ph = qkvh + gb;
    const __nv_bfloat16* pl = qkvl + gb;
    const int qo = h * HDIM;
    const int ko = GDIM + h * HDIM;
    const int vo = 2 * GDIM + h * HDIM;

    // stage KV tile jt into stage s: 4 planes x 64 rows x 8 chunks = 2048
    auto stage_kv = [&](int jt, int s) {
        const int j0 = jt * 64;
        #pragma unroll
        for (int j = 0; j < 8; ++j) {
            int cid = tid + 256 * j;
            int plane = cid >> 9;          // 0 Kh, 1 Kl, 2 Vh, 3 Vl
            int idx = cid & 511;
            int row = idx >> 3;
            int ch  = idx & 7;
            const __nv_bfloat16* bp = (plane & 1) ? pl : ph;
            int co = (plane >> 1) ? vo : ko;
            cp_async16(S + AKV0 + s * AKVS + plane * 9216 + (row * AP + ch * 8) * 2,
                       bp + (size_t)(j0 + row) * DIM + co + ch * 8);
        }
    };

    // Q stage: 2 planes x 128 rows x 8 chunks = 2048
    #pragma unroll
    for (int j = 0; j < 8; ++j) {
        int cid = tid + 256 * j;
        int plane = cid >> 10;
        int idx = cid & 1023;
        int row = idx >> 3;
        int ch  = idx & 7;
        const __nv_bfloat16* bp = plane ? pl : ph;
        cp_async16(S + plane * 18432 + (row * AP + ch * 8) * 2,
                   bp + (size_t)(q0 + row) * DIM + qo + ch * 8);
    }
    stage_kv(0, 0);
    cp_commit();       // group0 = Q + KV0

    uint32_t aqh[4][4], aql[4][4];
    bool qloaded = false;

    float m_[2] = {-1e30f, -1e30f};
    float l_[2] = {0.f, 0.f};
    float oacc[8][4];
    #pragma unroll
    for (int j = 0; j < 8; ++j)
        #pragma unroll
        for (int r = 0; r < 4; ++r) oacc[j][r] = 0.f;

    const int jt_max = (q0 + 127) >> 6;
    for (int jt = 0; jt <= jt_max; ++jt) {
        const int s = jt & 1;
        const bool more = jt < jt_max;
        if (more) {
            stage_kv(jt + 1, s ^ 1);
            cp_commit();
            cp_wait1();
        } else {
            cp_wait0();
        }
        __syncthreads();

        if (!qloaded) {
            qloaded = true;
            const int ar = w * 16 + (lane & 15);
            const int ak = (lane >> 4) * 8;
            #pragma unroll
            for (int ks = 0; ks < 4; ++ks) {
                uint32_t a = S + AQH + (ar * AP + ks * 16 + ak) * 2;
                ldsm_x4(aqh[ks], a);
                ldsm_x4(aql[ks], a + (AQL - AQH));
            }
        }

        const int j0 = jt * 64;
        if (j0 <= q0 + w * 16 + 15) {
            // ---- S = Q K^T (bf16x3) on stage s ----
            float sacc[8][4];
            #pragma unroll
            for (int j = 0; j < 8; ++j)
                #pragma unroll
                for (int r = 0; r < 4; ++r) sacc[j][r] = 0.f;

            {
                const int br  = (lane & 7) + ((lane >> 4) << 3);
                const int bkl = ((lane >> 3) & 1) * 8;
                const uint32_t KB = S + AKV0 + s * AKVS;
                #pragma unroll
                for (int ks = 0; ks < 4; ++ks) {
                    uint32_t bhf[4][4], blf[4][4];
                    #pragma unroll
                    for (int np = 0; np < 4; ++np) {
                        uint32_t a = KB + ((np * 16 + br) * AP + ks * 16 + bkl) * 2;
                        ldsm_x4(bhf[np], a);
                        ldsm_x4(blf[np], a + 9216);
                    }
                    #pragma unroll
                    for (int np = 0; np < 4; ++np) {
                        mma_bf16(sacc[2 * np],     aqh[ks], &bhf[np][0]);
                        mma_bf16(sacc[2 * np + 1], aqh[ks], &bhf[np][2]);
                    }
                    #pragma unroll
                    for (int np = 0; np < 4; ++np) {
                        mma_bf16(sacc[2 * np],     aqh[ks], &blf[np][0]);
                        mma_bf16(sacc[2 * np + 1], aqh[ks], &blf[np][2]);
                    }
                    #pragma unroll
                    for (int np = 0; np < 4; ++np) {
                        mma_bf16(sacc[2 * np],     aql[ks], &bhf[np][0]);
                        mma_bf16(sacc[2 * np + 1], aql[ks], &bhf[np][2]);
                    }
                }
            }

            // ---- scale + causal mask ----
            const int rbase = q0 + w * 16 + (lane >> 2);
            const int cbase = (lane & 3) * 2;
            const bool partial = (j0 + 63 > q0 + w * 16);
            #pragma unroll
            for (int j = 0; j < 8; ++j)
                #pragma unroll
                for (int rw = 0; rw < 2; ++rw)
                    #pragma unroll
                    for (int c = 0; c < 2; ++c) {
                        float v = sacc[j][rw * 2 + c] * 0.125f;
                        if (partial && (j0 + j * 8 + cbase + c > rbase + rw * 8))
                            v = -1e30f;
                        sacc[j][rw * 2 + c] = v;
                    }

            // ---- online softmax ----
            #pragma unroll
            for (int rw = 0; rw < 2; ++rw) {
                float rm = -1e30f;
                #pragma unroll
                for (int j = 0; j < 8; ++j) {
                    rm = fmaxf(rm, sacc[j][rw * 2]);
                    rm = fmaxf(rm, sacc[j][rw * 2 + 1]);
                }
                rm = fmaxf(rm, __shfl_xor_sync(0xffffffffu, rm, 1));
                rm = fmaxf(rm, __shfl_xor_sync(0xffffffffu, rm, 2));
                const float mnew  = fmaxf(m_[rw], rm);
                const float alpha = __expf(m_[rw] - mnew);
                m_[rw] = mnew;
                float rs = 0.f;
                #pragma unroll
                for (int j = 0; j < 8; ++j) {
                    float p0 = __expf(sacc[j][rw * 2]     - mnew);
                    float p1 = __expf(sacc[j][rw * 2 + 1] - mnew);
                    sacc[j][rw * 2]     = p0;
                    sacc[j][rw * 2 + 1] = p1;
                    rs += p0 + p1;
                }
                rs += __shfl_xor_sync(0xffffffffu, rs, 1);
                rs += __shfl_xor_sync(0xffffffffu, rs, 2);
                l_[rw] = l_[rw] * alpha + rs;
                #pragma unroll
                for (int j = 0; j < 8; ++j) {
                    oacc[j][rw * 2]     *= alpha;
                    oacc[j][rw * 2 + 1] *= alpha;
                }
            }

            // ---- P: C-frag -> A-frag, split hi/lo ----
            uint32_t ph4[4][4], pl4[4][4];
            #pragma unroll
            for (int u = 0; u < 4; ++u) {
                ph4[u][0] = packsplit(sacc[2 * u][0],     sacc[2 * u][1],     pl4[u][0]);
                ph4[u][1] = packsplit(sacc[2 * u][2],     sacc[2 * u][3],     pl4[u][1]);
                ph4[u][2] = packsplit(sacc[2 * u + 1][0], sacc[2 * u + 1][1], pl4[u][2]);
                ph4[u][3] = packsplit(sacc[2 * u + 1][2], sacc[2 * u + 1][3], pl4[u][3]);
            }

            // ---- O += P V, V [key][d] via ldmatrix.trans ----
            {
                const int vk = ((lane >> 3) & 1) * 8 + (lane & 7);
                const int vn = (lane >> 4) * 8;
                const uint32_t VB = S + AKV0 + s * AKVS + 18432;
                #pragma unroll
                for (int u = 0; u < 4; ++u) {
                    uint32_t bvh[4][4], bvl[4][4];
                    #pragma unroll
                    for (int np = 0; np < 4; ++np) {
                        uint32_t a = VB + ((u * 16 + vk) * AP + np * 16 + vn) * 2;
                        ldsm_x4t(bvh[np], a);
                        ldsm_x4t(bvl[np], a + 9216);
                    }
                    #pragma unroll
                    for (int np = 0; np < 4; ++np) {
                        mma_bf16(oacc[2 * np],     ph4[u], &bvh[np][0]);
                        mma_bf16(oacc[2 * np + 1], ph4[u], &bvh[np][2]);
                    }
                    #pragma unroll
                    for (int np = 0; np < 4; ++np) {
                        mma_bf16(oacc[2 * np],     ph4[u], &bvl[np][0]);
                        mma_bf16(oacc[2 * np + 1], ph4[u], &bvl[np][2]);
                    }
                    #pragma unroll
                    for (int np = 0; np < 4; ++np) {
                        mma_bf16(oacc[2 * np],     pl4[u], &bvh[np][0]);
                        mma_bf16(oacc[2 * np + 1], pl4[u], &bvh[np][2]);
                    }
                }
            }
        }
        __syncthreads();
    }

    // ---- finalize + write split planes ----
    #pragma unroll
    for (int rw = 0; rw < 2; ++rw) {
        const float inv = 1.0f / l_[rw];
        const size_t row = (size_t)b * SEQ + q0 + w * 16 + (lane >> 2) + rw * 8;
        const size_t off = row * DIM + g * GDIM + h * HDIM + (lane & 3) * 2;
        #pragma unroll
        for (int j = 0; j < 8; ++j) {
            uint32_t lo;
            uint32_t hi = packsplit(oacc[j][rw * 2] * inv,
                                    oacc[j][rw * 2 + 1] * inv, lo);
            *reinterpret_cast<uint32_t*>(attnh + off + j * 8) = hi;
            *reinterpret_cast<uint32_t*>(attnl + off + j * 8) = lo;
        }
    }
}

// ---------------------------------------------------------------------------
// PDE kernels: read fp32 u column, evolve, write split bf16 planes.
// ---------------------------------------------------------------------------
__global__ void pde_sg_kernel(const float* __restrict__ u,
                              __nv_bfloat16* __restrict__ uh,
                              __nv_bfloat16* __restrict__ ul)
{
    const int b = blockIdx.x >> 8;
    const int c = blockIdx.x & 255;
    const size_t base = (size_t)b * SEQ * DIM + c;
    __shared__ float su[SEQ], sw[SEQ];
    const int tid = threadIdx.x;
    for (int t = tid; t < SEQ; t += 256) { su[t] = u[base + (size_t)t * DIM]; sw[t] = 0.f; }
    __syncthreads();
    for (int step = 0; step < 3; ++step) {
        float dw[8];
        #pragma unroll
        for (int i = 0; i < 8; ++i) {
            int t = tid + i * 256;
            float um = (t > 0)       ? su[t - 1] : 0.f;
            float up = (t < SEQ - 1) ? su[t + 1] : 0.f;
            dw[i] = DT_F * ((um - 2.f * su[t] + up) - sinf(su[t]));
        }
        __syncthreads();
        #pragma unroll
        for (int i = 0; i < 8; ++i) {
            int t = tid + i * 256;
            sw[t] += dw[i];
            su[t] += DT_F * sw[t];
        }
        __syncthreads();
    }
    for (int t = tid; t < SEQ; t += 256) {
        __nv_bfloat16 h, l;
        split_bf(su[t], h, l);
        uh[base + (size_t)t * DIM] = h;
        ul[base + (size_t)t * DIM] = l;
    }
}

__global__ void pde_kdv_kernel(const float* __restrict__ u,
                               __nv_bfloat16* __restrict__ uh,
                               __nv_bfloat16* __restrict__ ul)
{
    const int b = blockIdx.x >> 8;
    const int c = blockIdx.x & 255;
    const size_t base = (size_t)b * SEQ * DIM + c;
    __shared__ float su[SEQ];
    const int tid = threadIdx.x;
    for (int t = tid; t < SEQ; t += 256) su[t] = u[base + (size_t)t * DIM];
    __syncthreads();
    for (int step = 0; step < 3; ++step) {
        float du[8];
        #pragma unroll
        for (int i = 0; i < 8; ++i) {
            int t = tid + i * 256;
            float um2 = (t > 1)       ? su[t - 2] : 0.f;
            float um1 = (t > 0)       ? su[t - 1] : 0.f;
            float up1 = (t < SEQ - 1) ? su[t + 1] : 0.f;
            float up2 = (t < SEQ - 2) ? su[t + 2] : 0.f;
            float d1 = 0.5f * (up1 - um1);
            float d3 = 0.5f * (up2 - 2.f * up1 + 2.f * um1 - um2);
            du[i] = DT_F * (-6.f * su[t] * d1 - d3);
        }
        __syncthreads();
        #pragma unroll
        for (int i = 0; i < 8; ++i) {
            int t = tid + i * 256;
            su[t] += du[i];
        }
        __syncthreads();
    }
    for (int t = tid; t < SEQ; t += 256) {
        __nv_bfloat16 h, l;
        split_bf(su[t], h, l);
        uh[base + (size_t)t * DIM] = h;
        ul[base + (size_t)t * DIM] = l;
    }
}

__global__ void pde_hj_kernel(const float* __restrict__ u,
                              __nv_bfloat16* __restrict__ uh,
                              __nv_bfloat16* __restrict__ ul)
{
    const int b = blockIdx.x >> 8;
    const int c = blockIdx.x & 255;
    const size_t base = (size_t)b * SEQ * DIM + c;
    __shared__ float su[SEQ], sw[SEQ], sf[SEQ];
    const int tid = threadIdx.x;
    for (int t = tid; t < SEQ; t += 256) { su[t] = u[base + (size_t)t * DIM]; sw[t] = 0.f; }
    __syncthreads();
    for (int step = 0; step < 3; ++step) {
        #pragma unroll
        for (int i = 0; i < 8; ++i) {
            int t = tid + i * 256;
            float v = su[t];
            sf[t] = v - v * v + v * v * v;
        }
        __syncthreads();
        float dw[8];
        #pragma unroll
        for (int i = 0; i < 8; ++i) {
            int t = tid + i * 256;
            float fm  = (t > 0)       ? sf[t - 1] : 0.f;
            float fp  = (t < SEQ - 1) ? sf[t + 1] : 0.f;
            float d2f = fm - 2.f * sf[t] + fp;
            float um2 = (t > 1)       ? su[t - 2] : 0.f;
            float um1 = (t > 0)       ? su[t - 1] : 0.f;
            float up1 = (t < SEQ - 1) ? su[t + 1] : 0.f;
            float up2 = (t < SEQ - 2) ? su[t + 2] : 0.f;
            float d4  = um2 - 4.f * um1 + 6.f * su[t] - 4.f * up1 + up2;
            dw[i] = DT_F * (d2f - HJ_HF * d4);
        }
        __syncthreads();
        #pragma unroll
        for (int i = 0; i < 8; ++i) {
            int t = tid + i * 256;
            sw[t] += dw[i];
            su[t] += DT_F * sw[t];
        }
        __syncthreads();
    }
    for (int t = tid; t < SEQ; t += 256) {
        __nv_bfloat16 h, l;
        split_bf(su[t], h, l);
        uh[base + (size_t)t * DIM] = h;
        ul[base + (size_t)t * DIM] = l;
    }
}

// ---------------------------------------------------------------------------
// Launch
// ---------------------------------------------------------------------------
extern "C" void kernel_launch(void* const* d_in, const int* in_sizes, int n_in,
                              void* d_out, int out_size)
{
    const float* x      = (const float*)d_in[0];
    const float* in_w   = (const float*)d_in[1];
    const float* in_b   = (const float*)d_in[2];
    const float* qkv_w[3] = {(const float*)d_in[3],  (const float*)d_in[7],  (const float*)d_in[11]};
    const float* qkv_b[3] = {(const float*)d_in[4],  (const float*)d_in[8],  (const float*)d_in[12]};
    const float* ow[3]    = {(const float*)d_in[5],  (const float*)d_in[9],  (const float*)d_in[13]};
    const float* ob[3]    = {(const float*)d_in[6],  (const float*)d_in[10], (const float*)d_in[14]};
    const float* out_w  = (const float*)d_in[15];
    const float* out_b  = (const float*)d_in[16];
    float* out = (float*)d_out;

    __nv_bfloat16 *xh, *xl, *hh, *hl, *qh, *ql, *ah, *al, *uh, *ul, *whi, *wlo;
    float* u;
    cudaGetSymbolAddress((void**)&xh, g_xh);  cudaGetSymbolAddress((void**)&xl, g_xl);
    cudaGetSymbolAddress((void**)&hh, g_hh);  cudaGetSymbolAddress((void**)&hl, g_hl);
    cudaGetSymbolAddress((void**)&qh, g_qh);  cudaGetSymbolAddress((void**)&ql, g_ql);
    cudaGetSymbolAddress((void**)&ah, g_ah);  cudaGetSymbolAddress((void**)&al, g_al);
    cudaGetSymbolAddress((void**)&uh, g_uh);  cudaGetSymbolAddress((void**)&ul, g_ul);
    cudaGetSymbolAddress((void**)&whi, g_whi); cudaGetSymbolAddress((void**)&wlo, g_wlo);
    cudaGetSymbolAddress((void**)&u, g_u);

    cudaFuncSetAttribute(attn_tc_kernel,
                         cudaFuncAttributeMaxDynamicSharedMemorySize, ATT_SMEM);
    cudaFuncSetAttribute(gemm_pp_kernel<true>,
                         cudaFuncAttributeMaxDynamicSharedMemorySize, GEMM_SMEM);
    cudaFuncSetAttribute(gemm_pp_kernel<false>,
                         cudaFuncAttributeMaxDynamicSharedMemorySize, GEMM_SMEM);

    // ---- weight prep ----
    WJobs jobs;
    jobs.W[0] = in_w;  jobs.hi[0] = whi + WT_IN;  jobs.lo[0] = wlo + WT_IN;
    jobs.K[0] = 768;   jobs.N[0] = 768;
    for (int g = 0; g < 3; ++g) {
        jobs.W[1 + g]  = qkv_w[g];
        jobs.hi[1 + g] = whi + WT_QKV0 + g * 768 * 256;
        jobs.lo[1 + g] = wlo + WT_QKV0 + g * 768 * 256;
        jobs.K[1 + g]  = 256; jobs.N[1 + g] = 768;
        jobs.W[4 + g]  = ow[g];
        jobs.hi[4 + g] = whi + WT_OW0 + g * 256 * 256;
        jobs.lo[4 + g] = wlo + WT_OW0 + g * 256 * 256;
        jobs.K[4 + g]  = 256; jobs.N[4 + g] = 256;
    }
    jobs.W[7] = out_w; jobs.hi[7] = whi + WT_OUT; jobs.lo[7] = wlo + WT_OUT;
    jobs.K[7] = 768;   jobs.N[7] = 768;
    wsplit_all_kernel<<<dim3(24, 24, 8), dim3(32, 8)>>>(jobs);

    // ---- split x ----
    asplit_kernel<<<MD / 1024, 256>>>(x, xh, xl, MD);

    // 1) h = x @ in_w + in_b  (split output)
    {
        GemmArgs a{};
        a.Ah[0] = xh; a.Al[0] = xl; a.lda = DIM; a.K = 768;
        a.Bh[0] = whi + WT_IN; a.Bl[0] = wlo + WT_IN; a.bias[0] = in_b;
        a.Ch[0] = hh; a.Cl[0] = hl; a.ldc = DIM;
        gemm_pp_kernel<true><<<dim3(6, 64, 1), 256, GEMM_SMEM>>>(a);
    }

    // 2) qkv (fused over groups, split output)
    {
        GemmArgs a{};
        for (int g = 0; g < 3; ++g) {
            a.Ah[g] = hh + g * GDIM; a.Al[g] = hl + g * GDIM;
            a.Bh[g] = whi + WT_QKV0 + g * 768 * 256;
            a.Bl[g] = wlo + WT_QKV0 + g * 768 * 256;
            a.bias[g] = qkv_b[g];
            a.Ch[g] = qh + (size_t)g * MD; a.Cl[g] = ql + (size_t)g * MD;
        }
        a.lda = DIM; a.K = 256; a.ldc = DIM;
        gemm_pp_kernel<true><<<dim3(6, 64, 3), 256, GEMM_SMEM>>>(a);
    }

    // 3) attention (split planes in and out)
    attn_tc_kernel<<<dim3(SEQ / 128, BATCH * 4, 3), 256, ATT_SMEM>>>(qh, ql, ah, al);

    // 4) out projection (fused, fp32 output into u)
    {
        GemmArgs a{};
        for (int g = 0; g < 3; ++g) {
            a.Ah[g] = ah + g * GDIM; a.Al[g] = al + g * GDIM;
            a.Bh[g] = whi + WT_OW0 + g * 256 * 256;
            a.Bl[g] = wlo + WT_OW0 + g * 256 * 256;
            a.bias[g] = ob[g];
            a.Cf[g] = u + g * GDIM;
        }
        a.lda = DIM; a.K = 256; a.ldc = DIM;
        gemm_pp_kernel<false><<<dim3(2, 64, 3), 256, GEMM_SMEM>>>(a);
    }

    // 5) PDE evolutions (write split planes)
    pde_sg_kernel <<<BATCH * GDIM, 256>>>(u + 0 * GDIM, uh + 0 * GDIM, ul + 0 * GDIM);
    pde_kdv_kernel<<<BATCH * GDIM, 256>>>(u + 1 * GDIM, uh + 1 * GDIM, ul + 1 * GDIM);
    pde_hj_kernel <<<BATCH * GDIM, 256>>>(u + 2 * GDIM, uh + 2 * GDIM, ul + 2 * GDIM);

    // 6) out = u @ out_w + out_b (fp32 output)
    {
        GemmArgs a{};
        a.Ah[0] = uh; a.Al[0] = ul; a.lda = DIM; a.K = 768;
        a.Bh[0] = whi + WT_OUT; a.Bl[0] = wlo + WT_OUT; a.bias[0] = out_b;
        a.Cf[0] = out; a.ldc = DIM;
        gemm_pp_kernel<false><<<dim3(6, 64, 1), 256, GEMM_SMEM>>>(a);
    }
}